// round 11
// baseline (speedup 1.0000x reference)
#include <cuda_runtime.h>
#include <cstdint>

#define Bb    8
#define Hh    512
#define Ll    8192
#define NFFT  16384
#define HALF  8192
#define QTOP  4096   /* NFFT/4 */
#define NPAIR 256    /* H/2 */
#define TFFT  1024
#define NTW   5461   /* 1+4+16+...+4096 */

// ---------------- scratch (device globals; no allocation allowed) ----------------
__device__ float4 g_AB[(size_t)NPAIR * (HALF + 1)];   // per-pair spectra, pointwise iteration order
__device__ float  g_ymid[(size_t)Bb * Hh * Ll];       // conv+skip result (B,H,L), tf32-rounded
__device__ float  g_Wr[(size_t)Hh * Hh];              // W pre-rounded to tf32 (rna)
__device__ float2 g_tw1[NTW];                         // twiddle LUT per (stage,j)
__device__ float2 g_tw2[NTW];
__device__ float2 g_tw3[NTW];

// ---------------- helpers ----------------
__device__ __forceinline__ float2 cmulf(float2 a, float2 b) {
    return make_float2(a.x * b.x - a.y * b.y, a.x * b.y + a.y * b.x);
}
__device__ __forceinline__ int rev4_14(int k) {
    unsigned r = __brev((unsigned)k) >> 18;
    return (int)(((r & 0x2AAAu) >> 1) | ((r & 0x1555u) << 1));
}
__device__ __forceinline__ float tf32r(float v) {
    uint32_t r;
    asm("cvt.rna.tf32.f32 %0, %1;" : "=r"(r) : "f"(v));
    return __uint_as_float(r);
}
// bank swizzle: XOR bits[4:6) into bit-pairs [0:2) and [2:4)
__device__ __forceinline__ int sw(int n) {
    return n ^ (((n >> 4) & 3) * 5);
}
// radix-4 DFT core
__device__ __forceinline__ void bf4(float2& a0, float2& a1, float2& a2, float2& a3) {
    float t0x = a0.x + a2.x, t0y = a0.y + a2.y;
    float t1x = a0.x - a2.x, t1y = a0.y - a2.y;
    float t2x = a1.x + a3.x, t2y = a1.y + a3.y;
    float t3x = a1.x - a3.x, t3y = a1.y - a3.y;
    a0 = make_float2(t0x + t2x, t0y + t2y);
    a1 = make_float2(t1x + t3y, t1y - t3x);   // t1 - i*t3
    a2 = make_float2(t0x - t2x, t0y - t2y);
    a3 = make_float2(t1x - t3y, t1y + t3x);   // t1 + i*t3
}

// ---------------- twiddle LUT init ----------------
__global__ void tw_init() {
    int idx = blockIdx.x * 256 + threadIdx.x;
    if (idx >= NTW) return;
    int q = 1, off = 0;
    while (idx >= off + q) { off += q; q <<= 2; }
    int j = idx - off;
    int m = q << 2;
    float ang = -6.283185307179586f * ((float)j / (float)m);
    float s1, c1, s2, c2, s3, c3;
    sincosf(ang, &s1, &c1);
    sincosf(2.0f * ang, &s2, &c2);
    sincosf(3.0f * ang, &s3, &c3);
    g_tw1[idx] = make_float2(c1, s1);
    g_tw2[idx] = make_float2(c2, s2);
    g_tw3[idx] = make_float2(c3, s3);
}

// ---------------- fused load + first DIF stage (m=NFFT, top half zero) ----------------
__device__ void dif_first_fused(float2* s, const float* __restrict__ f1,
                                const float* __restrict__ f2, int tid) {
#pragma unroll 2
    for (int i = tid; i < QTOP; i += TFFT) {
        float2 a0 = make_float2(f1[i], f2[i]);
        float2 a1 = make_float2(f1[i + QTOP], f2[i + QTOP]);
        float2 b0 = make_float2(a0.x + a1.x, a0.y + a1.y);
        float2 b1 = make_float2(a0.x + a1.y, a0.y - a1.x);   // a0 - i*a1
        float2 b2 = make_float2(a0.x - a1.x, a0.y - a1.y);
        float2 b3 = make_float2(a0.x - a1.y, a0.y + a1.x);   // a0 + i*a1
        float2 w1 = __ldg(&g_tw1[1365 + i]);
        float2 w2 = __ldg(&g_tw2[1365 + i]);
        float2 w3 = __ldg(&g_tw3[1365 + i]);
        s[sw(i)]            = b0;
        s[sw(i + QTOP)]     = cmulf(b1, w1);
        s[sw(i + 2 * QTOP)] = cmulf(b2, w2);
        s[sw(i + 3 * QTOP)] = cmulf(b3, w3);
    }
    __syncthreads();
}

// ---------------- merged radix-16 DIF pass: stages (m=4Q) then (m=Q), Q4 = Q/4 ----------------
// One 16-element group per thread; all register indices compile-time constant.
template<int Q>
__device__ __forceinline__ void dif_merged(float2* s, int tid) {
    constexpr int Q4   = Q / 4;
    constexpr int offA = (Q - 1) / 3;     // LUT offset for stage m=4Q (q=Q)
    constexpr int offB = (Q4 - 1) / 3;    // LUT offset for stage m=Q  (q=Q4)
    int j  = tid & (Q4 - 1);
    int g0 = (tid / Q4) * (16 * Q4) + j;
    float2 x[16];
#pragma unroll
    for (int b = 0; b < 4; ++b) {
        float2 a0 = s[sw(g0 + b * Q4)];
        float2 a1 = s[sw(g0 + Q + b * Q4)];
        float2 a2 = s[sw(g0 + 2 * Q + b * Q4)];
        float2 a3 = s[sw(g0 + 3 * Q + b * Q4)];
        bf4(a0, a1, a2, a3);
        int jA = j + b * Q4;
        float2 w1 = __ldg(&g_tw1[offA + jA]);
        float2 w2 = __ldg(&g_tw2[offA + jA]);
        float2 w3 = __ldg(&g_tw3[offA + jA]);
        x[b]      = a0;
        x[4 + b]  = cmulf(a1, w1);
        x[8 + b]  = cmulf(a2, w2);
        x[12 + b] = cmulf(a3, w3);
    }
    float2 v1 = __ldg(&g_tw1[offB + j]);
    float2 v2 = __ldg(&g_tw2[offB + j]);
    float2 v3 = __ldg(&g_tw3[offB + j]);
#pragma unroll
    for (int a = 0; a < 4; ++a) {
        bf4(x[4 * a], x[4 * a + 1], x[4 * a + 2], x[4 * a + 3]);
        int n0 = g0 + a * Q;
        s[sw(n0)]           = x[4 * a];
        s[sw(n0 + Q4)]      = cmulf(x[4 * a + 1], v1);
        s[sw(n0 + 2 * Q4)]  = cmulf(x[4 * a + 2], v2);
        s[sw(n0 + 3 * Q4)]  = cmulf(x[4 * a + 3], v3);
    }
    __syncthreads();
}

// ---------------- merged radix-16 DIT pass: stages (m=Q) then (m=4Q) ----------------
template<int Q>
__device__ __forceinline__ void dit_merged(float2* s, int tid) {
    constexpr int Q4   = Q / 4;
    constexpr int offA = (Q - 1) / 3;
    constexpr int offB = (Q4 - 1) / 3;
    int j  = tid & (Q4 - 1);
    int g0 = (tid / Q4) * (16 * Q4) + j;
    float2 x[16];
    float2 v1 = __ldg(&g_tw1[offB + j]);
    float2 v2 = __ldg(&g_tw2[offB + j]);
    float2 v3 = __ldg(&g_tw3[offB + j]);
#pragma unroll
    for (int a = 0; a < 4; ++a) {
        int n0 = g0 + a * Q;
        float2 c0 = s[sw(n0)];
        float2 c1 = s[sw(n0 + Q4)];
        float2 c2 = s[sw(n0 + 2 * Q4)];
        float2 c3 = s[sw(n0 + 3 * Q4)];
        c1 = cmulf(c1, v1);
        c2 = cmulf(c2, v2);
        c3 = cmulf(c3, v3);
        bf4(c0, c1, c2, c3);
        x[4 * a]     = c0;
        x[4 * a + 1] = c1;
        x[4 * a + 2] = c2;
        x[4 * a + 3] = c3;
    }
#pragma unroll
    for (int b = 0; b < 4; ++b) {
        int jA = j + b * Q4;
        float2 w1 = __ldg(&g_tw1[offA + jA]);
        float2 w2 = __ldg(&g_tw2[offA + jA]);
        float2 w3 = __ldg(&g_tw3[offA + jA]);
        float2 c0 = x[b];
        float2 c1 = cmulf(x[4 + b],  w1);
        float2 c2 = cmulf(x[8 + b],  w2);
        float2 c3 = cmulf(x[12 + b], w3);
        bf4(c0, c1, c2, c3);
        s[sw(g0 + b * Q4)]         = c0;
        s[sw(g0 + Q + b * Q4)]     = c1;
        s[sw(g0 + 2 * Q + b * Q4)] = c2;
        s[sw(g0 + 3 * Q + b * Q4)] = c3;
    }
    __syncthreads();
}

// ---------------- small DIF stages m = 16, 4 (sw keeps them conflict-free) ----------------
__device__ void dif_small(float2* s, int tid) {
#pragma unroll 1
    for (int m = 16; m >= 4; m >>= 2) {
        int q = m >> 2;
        int off = (q - 1) / 3;
#pragma unroll 2
        for (int i = tid; i < QTOP; i += TFFT) {
            int j = i & (q - 1);
            int base = ((i - j) << 2) + j;
            int i0 = sw(base), i1 = sw(base + q), i2 = sw(base + 2 * q), i3 = sw(base + 3 * q);
            float2 a0 = s[i0], a1 = s[i1], a2 = s[i2], a3 = s[i3];
            bf4(a0, a1, a2, a3);
            float2 w1 = __ldg(&g_tw1[off + j]);
            float2 w2 = __ldg(&g_tw2[off + j]);
            float2 w3 = __ldg(&g_tw3[off + j]);
            s[i0] = a0;
            s[i1] = cmulf(a1, w1);
            s[i2] = cmulf(a2, w2);
            s[i3] = cmulf(a3, w3);
        }
        __syncthreads();
    }
}

// ---------------- small DIT stages m = 4, 16 ----------------
__device__ void dit_small(float2* s, int tid) {
#pragma unroll 1
    for (int m = 4; m <= 16; m <<= 2) {
        int q = m >> 2;
        int off = (q - 1) / 3;
#pragma unroll 2
        for (int i = tid; i < QTOP; i += TFFT) {
            int j = i & (q - 1);
            int base = ((i - j) << 2) + j;
            int i0 = sw(base), i1 = sw(base + q), i2 = sw(base + 2 * q), i3 = sw(base + 3 * q);
            float2 c0 = s[i0], c1 = s[i1], c2 = s[i2], c3 = s[i3];
            float2 w1 = __ldg(&g_tw1[off + j]);
            float2 w2 = __ldg(&g_tw2[off + j]);
            float2 w3 = __ldg(&g_tw3[off + j]);
            c1 = cmulf(c1, w1);
            c2 = cmulf(c2, w2);
            c3 = cmulf(c3, w3);
            bf4(c0, c1, c2, c3);
            s[i0] = c0;
            s[i1] = c1;
            s[i2] = c2;
            s[i3] = c3;
        }
        __syncthreads();
    }
}

// ---------------- kernel 1: combined kernel spectra A,B per channel pair ----------------
__global__ void __launch_bounds__(TFFT, 1) kf_kernel(const float* __restrict__ K) {
    extern __shared__ float2 s[];
    int tid  = threadIdx.x;
    int pair = blockIdx.x;
    const float* k1 = K + (size_t)(2 * pair) * Ll;
    const float* k2 = K + (size_t)(2 * pair + 1) * Ll;
    dif_first_fused(s, k1, k2, tid);
    dif_merged<1024>(s, tid);
    dif_merged<64>(s, tid);
    dif_small(s, tid);

    const float inv = 1.0f / (4.0f * (float)NFFT);
    float4* AB = g_AB + (size_t)pair * (HALF + 1);
#pragma unroll 2
    for (int i = tid; i < HALF; i += TFFT) {
        int p  = ((i >> 1) << 2) | (i & 1);
        int k  = rev4_14(p);
        int kn = (NFFT - k) & (NFFT - 1);
        int p2 = rev4_14(kn);
        float2 Z  = s[sw(p)];
        float2 Zp = s[sw(p2)];
        float ax = (Z.x + Z.y + Zp.x + Zp.y) * inv;
        float ay = (Z.y - Z.x + Zp.x - Zp.y) * inv;
        float bx = (Z.x - Z.y + Zp.x - Zp.y) * inv;
        float by = (Z.x + Z.y - Zp.x - Zp.y) * inv;
        AB[i] = make_float4(ax, ay, bx, by);
    }
    if (tid == 0) {  // k = 8192 (slot 2), self-paired: Zp = Z
        float2 Z = s[sw(2)];
        float ax = 2.f * (Z.x + Z.y) * inv;
        float bx = 2.f * (Z.x - Z.y) * inv;
        AB[HALF] = make_float4(ax, 0.f, bx, 0.f);
    }
}

// ---------------- kernel 2: FFT conv + skip per (batch, channel pair) ----------------
__global__ void __launch_bounds__(TFFT, 1) conv_kernel(const float* __restrict__ u,
                                                       const float* __restrict__ D) {
    extern __shared__ float2 s[];
    int tid  = threadIdx.x;
    int pair = blockIdx.x & (NPAIR - 1);
    int b    = blockIdx.x >> 8;
    int h1   = 2 * pair, h2 = h1 + 1;
    const float* u1 = u + ((size_t)b * Hh + h1) * Ll;
    const float* u2 = u + ((size_t)b * Hh + h2) * Ll;
    dif_first_fused(s, u1, u2, tid);
    dif_merged<1024>(s, tid);
    dif_merged<64>(s, tid);
    dif_small(s, tid);

    // pointwise in slot order: p = 4*(i>>1)+(i&1) covers exactly k in [0,8192)
    const float4* AB = g_AB + (size_t)pair * (HALF + 1);
#pragma unroll 2
    for (int i = tid; i < HALF; i += TFFT) {
        int p  = ((i >> 1) << 2) | (i & 1);
        int k  = rev4_14(p);
        int kn = (NFFT - k) & (NFFT - 1);
        int p2 = rev4_14(kn);
        int sp = sw(p), sp2 = sw(p2);
        float2 Z  = s[sp];
        float2 Zp = s[sp2];
        float4 ab = AB[i];
        float vx = Z.x * ab.x - Z.y * ab.y + Zp.x * ab.z + Zp.y * ab.w;
        float vy = Z.x * ab.y + Z.y * ab.x - Zp.y * ab.z + Zp.x * ab.w;
        s[sp] = make_float2(vx, -vy);
        if (p != 0) {
            float wx =  Zp.x * ab.x + Zp.y * ab.y + Z.x * ab.z - Z.y * ab.w;
            float wy = -Zp.x * ab.y + Zp.y * ab.x - Z.x * ab.w - Z.y * ab.z;
            s[sp2] = make_float2(wx, -wy);
        }
    }
    if (tid == 0) {  // k = 8192 (slot 2), self-paired
        float2 Z = s[sw(2)];
        float4 ab = AB[HALF];
        float vx = Z.x * ab.x - Z.y * ab.y + Z.x * ab.z + Z.y * ab.w;
        float vy = Z.x * ab.y + Z.y * ab.x - Z.y * ab.z + Z.x * ab.w;
        s[sw(2)] = make_float2(vx, -vy);
    }
    __syncthreads();

    dit_small(s, tid);
    dit_merged<64>(s, tid);
    dit_merged<1024>(s, tid);

    // fused last DIT stage (m=NFFT): only outputs n<8192 kept; write y directly.
    float d1 = D[h1], d2 = D[h2];
    float* y1 = g_ymid + ((size_t)b * Hh + h1) * Ll;
    float* y2 = g_ymid + ((size_t)b * Hh + h2) * Ll;
#pragma unroll 2
    for (int i = tid; i < QTOP; i += TFFT) {
        float2 c0 = s[sw(i)], c1 = s[sw(i + QTOP)], c2 = s[sw(i + 2 * QTOP)], c3 = s[sw(i + 3 * QTOP)];
        float2 w1 = __ldg(&g_tw1[1365 + i]);
        float2 w2 = __ldg(&g_tw2[1365 + i]);
        float2 w3 = __ldg(&g_tw3[1365 + i]);
        c1 = cmulf(c1, w1);
        c2 = cmulf(c2, w2);
        c3 = cmulf(c3, w3);
        float t0x = c0.x + c2.x, t0y = c0.y + c2.y;
        float t1x = c0.x - c2.x, t1y = c0.y - c2.y;
        float t2x = c1.x + c3.x, t2y = c1.y + c3.y;
        float t3x = c1.x - c3.x, t3y = c1.y - c3.y;
        float o0x = t0x + t2x, o0y = t0y + t2y;
        float o1x = t1x + t3y, o1y = t1y - t3x;
        y1[i]        = tf32r( o0x + d1 * u1[i]);
        y2[i]        = tf32r(-o0y + d2 * u2[i]);
        y1[i + QTOP] = tf32r( o1x + d1 * u1[i + QTOP]);
        y2[i + QTOP] = tf32r(-o1y + d2 * u2[i + QTOP]);
    }
}

// ---------------- kernel 2.5: pre-round W to tf32 (round-to-nearest) ----------------
__global__ void wround_kernel(const float* __restrict__ W) {
    int i = blockIdx.x * 256 + threadIdx.x;
    g_Wr[i] = tf32r(W[i]);
}

// ================= kernel 3: tf32 mma.sync mix GEMM + tanh =================
#define MIXT 256
#define AS_STR 36
#define BS_STR 136
#define A_BYTES (128 * AS_STR * 4)
#define B_BYTES (32 * BS_STR * 4)
#define STAGE_BYTES (A_BYTES + B_BYTES)
#define MIX_SMEM (2 * STAGE_BYTES)

__device__ __forceinline__ uint32_t smem_u32(const void* p) {
    uint32_t a;
    asm("{ .reg .u64 t; cvta.to.shared.u64 t, %1; cvt.u32.u64 %0, t; }" : "=r"(a) : "l"(p));
    return a;
}
__device__ __forceinline__ void mma_tf32(float* c, const uint32_t* a, const uint32_t* b) {
    asm volatile(
        "mma.sync.aligned.m16n8k8.row.col.f32.tf32.tf32.f32 "
        "{%0,%1,%2,%3}, {%4,%5,%6,%7}, {%8,%9}, {%0,%1,%2,%3};"
        : "+f"(c[0]), "+f"(c[1]), "+f"(c[2]), "+f"(c[3])
        : "r"(a[0]), "r"(a[1]), "r"(a[2]), "r"(a[3]), "r"(b[0]), "r"(b[1]));
}
__device__ __forceinline__ void load_stage(const float* __restrict__ Wp,
                                           const float* __restrict__ Yp,
                                           uint32_t smem_stage, int c, int tid) {
    int k0 = c * 32;
#pragma unroll
    for (int i = 0; i < 4; ++i) {
        int idx = tid + i * MIXT;
        int row = idx >> 3, seg = idx & 7;
        const float* src = Wp + (size_t)row * Hh + k0 + seg * 4;
        uint32_t dst = smem_stage + (uint32_t)(row * AS_STR + seg * 4) * 4;
        asm volatile("cp.async.cg.shared.global [%0], [%1], 16;" :: "r"(dst), "l"(src));
    }
#pragma unroll
    for (int i = 0; i < 4; ++i) {
        int idx = tid + i * MIXT;
        int row = idx >> 5, seg = idx & 31;
        const float* src = Yp + (size_t)(k0 + row) * Ll + seg * 4;
        uint32_t dst = smem_stage + A_BYTES + (uint32_t)(row * BS_STR + seg * 4) * 4;
        asm volatile("cp.async.cg.shared.global [%0], [%1], 16;" :: "r"(dst), "l"(src));
    }
    asm volatile("cp.async.commit_group;" ::: "memory");
}

__global__ void __launch_bounds__(MIXT, 2) mix_tc_kernel(float* __restrict__ out) {
    extern __shared__ char smx[];
    uint32_t sb = smem_u32(smx);
    int tid  = threadIdx.x;
    int lane = tid & 31, wid = tid >> 5;
    int warpM = wid >> 2, warpN = wid & 3;
    int g = lane >> 2, tg = lane & 3;

    int b     = blockIdx.z;
    int pTile = blockIdx.y * 128;
    int lTile = blockIdx.x * 128;
    const float* Wp = g_Wr + (size_t)pTile * Hh;
    const float* Yp = g_ymid + (size_t)b * Hh * Ll + lTile;
    float* Ob = out + (size_t)b * Hh * Ll;

    float acc[4][4][4];
#pragma unroll
    for (int mt = 0; mt < 4; ++mt)
#pragma unroll
        for (int nt = 0; nt < 4; ++nt)
#pragma unroll
            for (int r = 0; r < 4; ++r) acc[mt][nt][r] = 0.f;

    load_stage(Wp, Yp, sb, 0, tid);

#pragma unroll 1
    for (int c = 0; c < Hh / 32; ++c) {
        if (c + 1 < Hh / 32) {
            load_stage(Wp, Yp, sb + ((c + 1) & 1) * STAGE_BYTES, c + 1, tid);
            asm volatile("cp.async.wait_group 1;" ::: "memory");
        } else {
            asm volatile("cp.async.wait_group 0;" ::: "memory");
        }
        __syncthreads();

        const float* As = (const float*)(smx + (c & 1) * STAGE_BYTES);
        const float* Bs = (const float*)(smx + (c & 1) * STAGE_BYTES + A_BYTES);
#pragma unroll
        for (int ks = 0; ks < 4; ++ks) {
            uint32_t af[4][4], bf[4][2];
            int kc = ks * 8 + tg;
#pragma unroll
            for (int mt = 0; mt < 4; ++mt) {
                int r0 = warpM * 64 + mt * 16 + g;
                af[mt][0] = __float_as_uint(As[r0 * AS_STR + kc]);
                af[mt][1] = __float_as_uint(As[(r0 + 8) * AS_STR + kc]);
                af[mt][2] = __float_as_uint(As[r0 * AS_STR + kc + 4]);
                af[mt][3] = __float_as_uint(As[(r0 + 8) * AS_STR + kc + 4]);
            }
#pragma unroll
            for (int nt = 0; nt < 4; ++nt) {
                int l = warpN * 32 + nt * 8 + g;
                bf[nt][0] = __float_as_uint(Bs[kc * BS_STR + l]);
                bf[nt][1] = __float_as_uint(Bs[(kc + 4) * BS_STR + l]);
            }
#pragma unroll
            for (int mt = 0; mt < 4; ++mt)
#pragma unroll
                for (int nt = 0; nt < 4; ++nt)
                    mma_tf32(acc[mt][nt], af[mt], bf[nt]);
        }
        __syncthreads();
    }

#pragma unroll
    for (int mt = 0; mt < 4; ++mt) {
        int p0 = pTile + warpM * 64 + mt * 16 + g;
#pragma unroll
        for (int nt = 0; nt < 4; ++nt) {
            int l = lTile + warpN * 32 + nt * 8 + 2 * tg;
            float2 v0 = make_float2(tanhf(acc[mt][nt][0]), tanhf(acc[mt][nt][1]));
            float2 v1 = make_float2(tanhf(acc[mt][nt][2]), tanhf(acc[mt][nt][3]));
            *(float2*)(Ob + (size_t)p0 * Ll + l)       = v0;
            *(float2*)(Ob + (size_t)(p0 + 8) * Ll + l) = v1;
        }
    }
}

// ---------------- launch ----------------
extern "C" void kernel_launch(void* const* d_in, const int* in_sizes, int n_in,
                              void* d_out, int out_size) {
    const float* u = (const float*)d_in[0];
    const float* K = (const float*)d_in[1];
    const float* D = (const float*)d_in[2];
    const float* W = (const float*)d_in[3];
    float* out = (float*)d_out;

    const int smem = NFFT * (int)sizeof(float2);  // 128 KB
    cudaFuncSetAttribute(kf_kernel,   cudaFuncAttributeMaxDynamicSharedMemorySize, smem);
    cudaFuncSetAttribute(conv_kernel, cudaFuncAttributeMaxDynamicSharedMemorySize, smem);
    cudaFuncSetAttribute(mix_tc_kernel, cudaFuncAttributeMaxDynamicSharedMemorySize, MIX_SMEM);

    tw_init<<<(NTW + 255) / 256, 256>>>();
    wround_kernel<<<(Hh * Hh) / 256, 256>>>(W);
    kf_kernel<<<NPAIR, TFFT, smem>>>(K);
    conv_kernel<<<Bb * NPAIR, TFFT, smem>>>(u, D);
    dim3 g(Ll / 128, Hh / 128, Bb);
    mix_tc_kernel<<<g, MIXT, MIX_SMEM>>>(out);
}

// round 12
// speedup vs baseline: 1.5289x; 1.5289x over previous
#include <cuda_runtime.h>
#include <cstdint>

#define Bb    8
#define Hh    512
#define Ll    8192
#define NFFT  16384
#define HALF  8192
#define QTOP  4096   /* NFFT/4 */
#define NPAIR 256    /* H/2 */
#define TFFT  512
#define NTW   5461   /* 1+4+16+...+4096 */

// ---------------- scratch (device globals; no allocation allowed) ----------------
__device__ float4 g_AB[(size_t)NPAIR * (HALF + 1)];   // per-pair spectra, pointwise iteration order
__device__ float  g_ymid[(size_t)Bb * Hh * Ll];       // conv+skip result (B,H,L), tf32-rounded
__device__ float  g_Wr[(size_t)Hh * Hh];              // W pre-rounded to tf32 (rna)
__device__ float2 g_tw1[NTW];                         // twiddle LUT per (stage,j)
__device__ float2 g_tw2[NTW];
__device__ float2 g_tw3[NTW];

// ---------------- helpers ----------------
__device__ __forceinline__ float2 cmulf(float2 a, float2 b) {
    return make_float2(a.x * b.x - a.y * b.y, a.x * b.y + a.y * b.x);
}
__device__ __forceinline__ int rev4_14(int k) {
    unsigned r = __brev((unsigned)k) >> 18;
    return (int)(((r & 0x2AAAu) >> 1) | ((r & 0x1555u) << 1));
}
__device__ __forceinline__ float tf32r(float v) {
    uint32_t r;
    asm("cvt.rna.tf32.f32 %0, %1;" : "=r"(r) : "f"(v));
    return __uint_as_float(r);
}
// bank swizzle: XOR bits[4:6) into bit-pairs [0:2) and [2:4)
__device__ __forceinline__ int sw(int n) {
    return n ^ (((n >> 4) & 3) * 5);
}
// radix-4 DFT core
__device__ __forceinline__ void bf4(float2& a0, float2& a1, float2& a2, float2& a3) {
    float t0x = a0.x + a2.x, t0y = a0.y + a2.y;
    float t1x = a0.x - a2.x, t1y = a0.y - a2.y;
    float t2x = a1.x + a3.x, t2y = a1.y + a3.y;
    float t3x = a1.x - a3.x, t3y = a1.y - a3.y;
    a0 = make_float2(t0x + t2x, t0y + t2y);
    a1 = make_float2(t1x + t3y, t1y - t3x);   // t1 - i*t3
    a2 = make_float2(t0x - t2x, t0y - t2y);
    a3 = make_float2(t1x - t3y, t1y + t3x);   // t1 + i*t3
}

// ---------------- twiddle LUT init ----------------
__global__ void tw_init() {
    int idx = blockIdx.x * 256 + threadIdx.x;
    if (idx >= NTW) return;
    int q = 1, off = 0;
    while (idx >= off + q) { off += q; q <<= 2; }
    int j = idx - off;
    int m = q << 2;
    float ang = -6.283185307179586f * ((float)j / (float)m);
    float s1, c1, s2, c2, s3, c3;
    sincosf(ang, &s1, &c1);
    sincosf(2.0f * ang, &s2, &c2);
    sincosf(3.0f * ang, &s3, &c3);
    g_tw1[idx] = make_float2(c1, s1);
    g_tw2[idx] = make_float2(c2, s2);
    g_tw3[idx] = make_float2(c3, s3);
}

// ---------------- fused load + first DIF stage (m=NFFT, top half zero) ----------------
__device__ void dif_first_fused(float2* s, const float* __restrict__ f1,
                                const float* __restrict__ f2, int tid) {
#pragma unroll 2
    for (int i = tid; i < QTOP; i += TFFT) {
        float2 a0 = make_float2(f1[i], f2[i]);
        float2 a1 = make_float2(f1[i + QTOP], f2[i + QTOP]);
        float2 b0 = make_float2(a0.x + a1.x, a0.y + a1.y);
        float2 b1 = make_float2(a0.x + a1.y, a0.y - a1.x);   // a0 - i*a1
        float2 b2 = make_float2(a0.x - a1.x, a0.y - a1.y);
        float2 b3 = make_float2(a0.x - a1.y, a0.y + a1.x);   // a0 + i*a1
        float2 w1 = __ldg(&g_tw1[1365 + i]);
        float2 w2 = __ldg(&g_tw2[1365 + i]);
        float2 w3 = __ldg(&g_tw3[1365 + i]);
        s[sw(i)]            = b0;
        s[sw(i + QTOP)]     = cmulf(b1, w1);
        s[sw(i + 2 * QTOP)] = cmulf(b2, w2);
        s[sw(i + 3 * QTOP)] = cmulf(b3, w3);
    }
    __syncthreads();
}

// ---------------- merged radix-16 DIF pass: stages (m=4Q) then (m=Q), Q4 = Q/4 ----------------
// NFFT/16 groups; all register indices compile-time constant. Needs >64 regs -> TFFT=512.
template<int Q>
__device__ __forceinline__ void dif_merged(float2* s, int tid) {
    constexpr int Q4   = Q / 4;
    constexpr int offA = (Q - 1) / 3;     // LUT offset for stage m=4Q (q=Q)
    constexpr int offB = (Q4 - 1) / 3;    // LUT offset for stage m=Q  (q=Q4)
#pragma unroll 1
    for (int i = tid; i < NFFT / 16; i += TFFT) {
        int j  = i & (Q4 - 1);
        int g0 = (i / Q4) * (16 * Q4) + j;
        float2 x[16];
#pragma unroll
        for (int b = 0; b < 4; ++b) {
            float2 a0 = s[sw(g0 + b * Q4)];
            float2 a1 = s[sw(g0 + Q + b * Q4)];
            float2 a2 = s[sw(g0 + 2 * Q + b * Q4)];
            float2 a3 = s[sw(g0 + 3 * Q + b * Q4)];
            bf4(a0, a1, a2, a3);
            int jA = j + b * Q4;
            float2 w1 = __ldg(&g_tw1[offA + jA]);
            float2 w2 = __ldg(&g_tw2[offA + jA]);
            float2 w3 = __ldg(&g_tw3[offA + jA]);
            x[b]      = a0;
            x[4 + b]  = cmulf(a1, w1);
            x[8 + b]  = cmulf(a2, w2);
            x[12 + b] = cmulf(a3, w3);
        }
        float2 v1 = __ldg(&g_tw1[offB + j]);
        float2 v2 = __ldg(&g_tw2[offB + j]);
        float2 v3 = __ldg(&g_tw3[offB + j]);
#pragma unroll
        for (int a = 0; a < 4; ++a) {
            bf4(x[4 * a], x[4 * a + 1], x[4 * a + 2], x[4 * a + 3]);
            int n0 = g0 + a * Q;
            s[sw(n0)]           = x[4 * a];
            s[sw(n0 + Q4)]      = cmulf(x[4 * a + 1], v1);
            s[sw(n0 + 2 * Q4)]  = cmulf(x[4 * a + 2], v2);
            s[sw(n0 + 3 * Q4)]  = cmulf(x[4 * a + 3], v3);
        }
    }
    __syncthreads();
}

// ---------------- merged radix-16 DIT pass: stages (m=Q) then (m=4Q) ----------------
template<int Q>
__device__ __forceinline__ void dit_merged(float2* s, int tid) {
    constexpr int Q4   = Q / 4;
    constexpr int offA = (Q - 1) / 3;
    constexpr int offB = (Q4 - 1) / 3;
#pragma unroll 1
    for (int i = tid; i < NFFT / 16; i += TFFT) {
        int j  = i & (Q4 - 1);
        int g0 = (i / Q4) * (16 * Q4) + j;
        float2 x[16];
        float2 v1 = __ldg(&g_tw1[offB + j]);
        float2 v2 = __ldg(&g_tw2[offB + j]);
        float2 v3 = __ldg(&g_tw3[offB + j]);
#pragma unroll
        for (int a = 0; a < 4; ++a) {
            int n0 = g0 + a * Q;
            float2 c0 = s[sw(n0)];
            float2 c1 = s[sw(n0 + Q4)];
            float2 c2 = s[sw(n0 + 2 * Q4)];
            float2 c3 = s[sw(n0 + 3 * Q4)];
            c1 = cmulf(c1, v1);
            c2 = cmulf(c2, v2);
            c3 = cmulf(c3, v3);
            bf4(c0, c1, c2, c3);
            x[4 * a]     = c0;
            x[4 * a + 1] = c1;
            x[4 * a + 2] = c2;
            x[4 * a + 3] = c3;
        }
#pragma unroll
        for (int b = 0; b < 4; ++b) {
            int jA = j + b * Q4;
            float2 w1 = __ldg(&g_tw1[offA + jA]);
            float2 w2 = __ldg(&g_tw2[offA + jA]);
            float2 w3 = __ldg(&g_tw3[offA + jA]);
            float2 c0 = x[b];
            float2 c1 = cmulf(x[4 + b],  w1);
            float2 c2 = cmulf(x[8 + b],  w2);
            float2 c3 = cmulf(x[12 + b], w3);
            bf4(c0, c1, c2, c3);
            s[sw(g0 + b * Q4)]         = c0;
            s[sw(g0 + Q + b * Q4)]     = c1;
            s[sw(g0 + 2 * Q + b * Q4)] = c2;
            s[sw(g0 + 3 * Q + b * Q4)] = c3;
        }
    }
    __syncthreads();
}

// ---------------- small DIF stages m = 16, 4 (sw keeps them conflict-free) ----------------
__device__ void dif_small(float2* s, int tid) {
#pragma unroll 1
    for (int m = 16; m >= 4; m >>= 2) {
        int q = m >> 2;
        int off = (q - 1) / 3;
#pragma unroll 2
        for (int i = tid; i < QTOP; i += TFFT) {
            int j = i & (q - 1);
            int base = ((i - j) << 2) + j;
            int i0 = sw(base), i1 = sw(base + q), i2 = sw(base + 2 * q), i3 = sw(base + 3 * q);
            float2 a0 = s[i0], a1 = s[i1], a2 = s[i2], a3 = s[i3];
            bf4(a0, a1, a2, a3);
            float2 w1 = __ldg(&g_tw1[off + j]);
            float2 w2 = __ldg(&g_tw2[off + j]);
            float2 w3 = __ldg(&g_tw3[off + j]);
            s[i0] = a0;
            s[i1] = cmulf(a1, w1);
            s[i2] = cmulf(a2, w2);
            s[i3] = cmulf(a3, w3);
        }
        __syncthreads();
    }
}

// ---------------- small DIT stages m = 4, 16 ----------------
__device__ void dit_small(float2* s, int tid) {
#pragma unroll 1
    for (int m = 4; m <= 16; m <<= 2) {
        int q = m >> 2;
        int off = (q - 1) / 3;
#pragma unroll 2
        for (int i = tid; i < QTOP; i += TFFT) {
            int j = i & (q - 1);
            int base = ((i - j) << 2) + j;
            int i0 = sw(base), i1 = sw(base + q), i2 = sw(base + 2 * q), i3 = sw(base + 3 * q);
            float2 c0 = s[i0], c1 = s[i1], c2 = s[i2], c3 = s[i3];
            float2 w1 = __ldg(&g_tw1[off + j]);
            float2 w2 = __ldg(&g_tw2[off + j]);
            float2 w3 = __ldg(&g_tw3[off + j]);
            c1 = cmulf(c1, w1);
            c2 = cmulf(c2, w2);
            c3 = cmulf(c3, w3);
            bf4(c0, c1, c2, c3);
            s[i0] = c0;
            s[i1] = c1;
            s[i2] = c2;
            s[i3] = c3;
        }
        __syncthreads();
    }
}

// ---------------- kernel 1: combined kernel spectra A,B per channel pair ----------------
__global__ void __launch_bounds__(TFFT, 1) kf_kernel(const float* __restrict__ K) {
    extern __shared__ float2 s[];
    int tid  = threadIdx.x;
    int pair = blockIdx.x;
    const float* k1 = K + (size_t)(2 * pair) * Ll;
    const float* k2 = K + (size_t)(2 * pair + 1) * Ll;
    dif_first_fused(s, k1, k2, tid);
    dif_merged<1024>(s, tid);
    dif_merged<64>(s, tid);
    dif_small(s, tid);

    const float inv = 1.0f / (4.0f * (float)NFFT);
    float4* AB = g_AB + (size_t)pair * (HALF + 1);
#pragma unroll 2
    for (int i = tid; i < HALF; i += TFFT) {
        int p  = ((i >> 1) << 2) | (i & 1);
        int k  = rev4_14(p);
        int kn = (NFFT - k) & (NFFT - 1);
        int p2 = rev4_14(kn);
        float2 Z  = s[sw(p)];
        float2 Zp = s[sw(p2)];
        float ax = (Z.x + Z.y + Zp.x + Zp.y) * inv;
        float ay = (Z.y - Z.x + Zp.x - Zp.y) * inv;
        float bx = (Z.x - Z.y + Zp.x - Zp.y) * inv;
        float by = (Z.x + Z.y - Zp.x - Zp.y) * inv;
        AB[i] = make_float4(ax, ay, bx, by);
    }
    if (tid == 0) {  // k = 8192 (slot 2), self-paired: Zp = Z
        float2 Z = s[sw(2)];
        float ax = 2.f * (Z.x + Z.y) * inv;
        float bx = 2.f * (Z.x - Z.y) * inv;
        AB[HALF] = make_float4(ax, 0.f, bx, 0.f);
    }
}

// ---------------- kernel 2: FFT conv + skip per (batch, channel pair) ----------------
__global__ void __launch_bounds__(TFFT, 1) conv_kernel(const float* __restrict__ u,
                                                       const float* __restrict__ D) {
    extern __shared__ float2 s[];
    int tid  = threadIdx.x;
    int pair = blockIdx.x & (NPAIR - 1);
    int b    = blockIdx.x >> 8;
    int h1   = 2 * pair, h2 = h1 + 1;
    const float* u1 = u + ((size_t)b * Hh + h1) * Ll;
    const float* u2 = u + ((size_t)b * Hh + h2) * Ll;
    dif_first_fused(s, u1, u2, tid);
    dif_merged<1024>(s, tid);
    dif_merged<64>(s, tid);
    dif_small(s, tid);

    // pointwise in slot order: p = 4*(i>>1)+(i&1) covers exactly k in [0,8192)
    const float4* AB = g_AB + (size_t)pair * (HALF + 1);
#pragma unroll 2
    for (int i = tid; i < HALF; i += TFFT) {
        int p  = ((i >> 1) << 2) | (i & 1);
        int k  = rev4_14(p);
        int kn = (NFFT - k) & (NFFT - 1);
        int p2 = rev4_14(kn);
        int sp = sw(p), sp2 = sw(p2);
        float2 Z  = s[sp];
        float2 Zp = s[sp2];
        float4 ab = AB[i];
        float vx = Z.x * ab.x - Z.y * ab.y + Zp.x * ab.z + Zp.y * ab.w;
        float vy = Z.x * ab.y + Z.y * ab.x - Zp.y * ab.z + Zp.x * ab.w;
        s[sp] = make_float2(vx, -vy);
        if (p != 0) {
            float wx =  Zp.x * ab.x + Zp.y * ab.y + Z.x * ab.z - Z.y * ab.w;
            float wy = -Zp.x * ab.y + Zp.y * ab.x - Z.x * ab.w - Z.y * ab.z;
            s[sp2] = make_float2(wx, -wy);
        }
    }
    if (tid == 0) {  // k = 8192 (slot 2), self-paired
        float2 Z = s[sw(2)];
        float4 ab = AB[HALF];
        float vx = Z.x * ab.x - Z.y * ab.y + Z.x * ab.z + Z.y * ab.w;
        float vy = Z.x * ab.y + Z.y * ab.x - Z.y * ab.z + Z.x * ab.w;
        s[sw(2)] = make_float2(vx, -vy);
    }
    __syncthreads();

    dit_small(s, tid);
    dit_merged<64>(s, tid);
    dit_merged<1024>(s, tid);

    // fused last DIT stage (m=NFFT): only outputs n<8192 kept; write y directly.
    float d1 = D[h1], d2 = D[h2];
    float* y1 = g_ymid + ((size_t)b * Hh + h1) * Ll;
    float* y2 = g_ymid + ((size_t)b * Hh + h2) * Ll;
#pragma unroll 2
    for (int i = tid; i < QTOP; i += TFFT) {
        float2 c0 = s[sw(i)], c1 = s[sw(i + QTOP)], c2 = s[sw(i + 2 * QTOP)], c3 = s[sw(i + 3 * QTOP)];
        float2 w1 = __ldg(&g_tw1[1365 + i]);
        float2 w2 = __ldg(&g_tw2[1365 + i]);
        float2 w3 = __ldg(&g_tw3[1365 + i]);
        c1 = cmulf(c1, w1);
        c2 = cmulf(c2, w2);
        c3 = cmulf(c3, w3);
        float t0x = c0.x + c2.x, t0y = c0.y + c2.y;
        float t1x = c0.x - c2.x, t1y = c0.y - c2.y;
        float t2x = c1.x + c3.x, t2y = c1.y + c3.y;
        float t3x = c1.x - c3.x, t3y = c1.y - c3.y;
        float o0x = t0x + t2x, o0y = t0y + t2y;
        float o1x = t1x + t3y, o1y = t1y - t3x;
        y1[i]        = tf32r( o0x + d1 * u1[i]);
        y2[i]        = tf32r(-o0y + d2 * u2[i]);
        y1[i + QTOP] = tf32r( o1x + d1 * u1[i + QTOP]);
        y2[i + QTOP] = tf32r(-o1y + d2 * u2[i + QTOP]);
    }
}

// ---------------- kernel 2.5: pre-round W to tf32 (round-to-nearest) ----------------
__global__ void wround_kernel(const float* __restrict__ W) {
    int i = blockIdx.x * 256 + threadIdx.x;
    g_Wr[i] = tf32r(W[i]);
}

// ================= kernel 3: tf32 mma.sync mix GEMM + tanh =================
#define MIXT 256
#define AS_STR 36
#define BS_STR 136
#define A_BYTES (128 * AS_STR * 4)
#define B_BYTES (32 * BS_STR * 4)
#define STAGE_BYTES (A_BYTES + B_BYTES)
#define MIX_SMEM (2 * STAGE_BYTES)

__device__ __forceinline__ uint32_t smem_u32(const void* p) {
    uint32_t a;
    asm("{ .reg .u64 t; cvta.to.shared.u64 t, %1; cvt.u32.u64 %0, t; }" : "=r"(a) : "l"(p));
    return a;
}
__device__ __forceinline__ void mma_tf32(float* c, const uint32_t* a, const uint32_t* b) {
    asm volatile(
        "mma.sync.aligned.m16n8k8.row.col.f32.tf32.tf32.f32 "
        "{%0,%1,%2,%3}, {%4,%5,%6,%7}, {%8,%9}, {%0,%1,%2,%3};"
        : "+f"(c[0]), "+f"(c[1]), "+f"(c[2]), "+f"(c[3])
        : "r"(a[0]), "r"(a[1]), "r"(a[2]), "r"(a[3]), "r"(b[0]), "r"(b[1]));
}
__device__ __forceinline__ void load_stage(const float* __restrict__ Wp,
                                           const float* __restrict__ Yp,
                                           uint32_t smem_stage, int c, int tid) {
    int k0 = c * 32;
#pragma unroll
    for (int i = 0; i < 4; ++i) {
        int idx = tid + i * MIXT;
        int row = idx >> 3, seg = idx & 7;
        const float* src = Wp + (size_t)row * Hh + k0 + seg * 4;
        uint32_t dst = smem_stage + (uint32_t)(row * AS_STR + seg * 4) * 4;
        asm volatile("cp.async.cg.shared.global [%0], [%1], 16;" :: "r"(dst), "l"(src));
    }
#pragma unroll
    for (int i = 0; i < 4; ++i) {
        int idx = tid + i * MIXT;
        int row = idx >> 5, seg = idx & 31;
        const float* src = Yp + (size_t)(k0 + row) * Ll + seg * 4;
        uint32_t dst = smem_stage + A_BYTES + (uint32_t)(row * BS_STR + seg * 4) * 4;
        asm volatile("cp.async.cg.shared.global [%0], [%1], 16;" :: "r"(dst), "l"(src));
    }
    asm volatile("cp.async.commit_group;" ::: "memory");
}

__global__ void __launch_bounds__(MIXT, 2) mix_tc_kernel(float* __restrict__ out) {
    extern __shared__ char smx[];
    uint32_t sb = smem_u32(smx);
    int tid  = threadIdx.x;
    int lane = tid & 31, wid = tid >> 5;
    int warpM = wid >> 2, warpN = wid & 3;
    int g = lane >> 2, tg = lane & 3;

    int b     = blockIdx.z;
    int pTile = blockIdx.y * 128;
    int lTile = blockIdx.x * 128;
    const float* Wp = g_Wr + (size_t)pTile * Hh;
    const float* Yp = g_ymid + (size_t)b * Hh * Ll + lTile;
    float* Ob = out + (size_t)b * Hh * Ll;

    float acc[4][4][4];
#pragma unroll
    for (int mt = 0; mt < 4; ++mt)
#pragma unroll
        for (int nt = 0; nt < 4; ++nt)
#pragma unroll
            for (int r = 0; r < 4; ++r) acc[mt][nt][r] = 0.f;

    load_stage(Wp, Yp, sb, 0, tid);

#pragma unroll 1
    for (int c = 0; c < Hh / 32; ++c) {
        if (c + 1 < Hh / 32) {
            load_stage(Wp, Yp, sb + ((c + 1) & 1) * STAGE_BYTES, c + 1, tid);
            asm volatile("cp.async.wait_group 1;" ::: "memory");
        } else {
            asm volatile("cp.async.wait_group 0;" ::: "memory");
        }
        __syncthreads();

        const float* As = (const float*)(smx + (c & 1) * STAGE_BYTES);
        const float* Bs = (const float*)(smx + (c & 1) * STAGE_BYTES + A_BYTES);
#pragma unroll
        for (int ks = 0; ks < 4; ++ks) {
            uint32_t af[4][4], bf[4][2];
            int kc = ks * 8 + tg;
#pragma unroll
            for (int mt = 0; mt < 4; ++mt) {
                int r0 = warpM * 64 + mt * 16 + g;
                af[mt][0] = __float_as_uint(As[r0 * AS_STR + kc]);
                af[mt][1] = __float_as_uint(As[(r0 + 8) * AS_STR + kc]);
                af[mt][2] = __float_as_uint(As[r0 * AS_STR + kc + 4]);
                af[mt][3] = __float_as_uint(As[(r0 + 8) * AS_STR + kc + 4]);
            }
#pragma unroll
            for (int nt = 0; nt < 4; ++nt) {
                int l = warpN * 32 + nt * 8 + g;
                bf[nt][0] = __float_as_uint(Bs[kc * BS_STR + l]);
                bf[nt][1] = __float_as_uint(Bs[(kc + 4) * BS_STR + l]);
            }
#pragma unroll
            for (int mt = 0; mt < 4; ++mt)
#pragma unroll
                for (int nt = 0; nt < 4; ++nt)
                    mma_tf32(acc[mt][nt], af[mt], bf[nt]);
        }
        __syncthreads();
    }

#pragma unroll
    for (int mt = 0; mt < 4; ++mt) {
        int p0 = pTile + warpM * 64 + mt * 16 + g;
#pragma unroll
        for (int nt = 0; nt < 4; ++nt) {
            int l = lTile + warpN * 32 + nt * 8 + 2 * tg;
            float2 v0 = make_float2(tanhf(acc[mt][nt][0]), tanhf(acc[mt][nt][1]));
            float2 v1 = make_float2(tanhf(acc[mt][nt][2]), tanhf(acc[mt][nt][3]));
            *(float2*)(Ob + (size_t)p0 * Ll + l)       = v0;
            *(float2*)(Ob + (size_t)(p0 + 8) * Ll + l) = v1;
        }
    }
}

// ---------------- launch ----------------
extern "C" void kernel_launch(void* const* d_in, const int* in_sizes, int n_in,
                              void* d_out, int out_size) {
    const float* u = (const float*)d_in[0];
    const float* K = (const float*)d_in[1];
    const float* D = (const float*)d_in[2];
    const float* W = (const float*)d_in[3];
    float* out = (float*)d_out;

    const int smem = NFFT * (int)sizeof(float2);  // 128 KB
    cudaFuncSetAttribute(kf_kernel,   cudaFuncAttributeMaxDynamicSharedMemorySize, smem);
    cudaFuncSetAttribute(conv_kernel, cudaFuncAttributeMaxDynamicSharedMemorySize, smem);
    cudaFuncSetAttribute(mix_tc_kernel, cudaFuncAttributeMaxDynamicSharedMemorySize, MIX_SMEM);

    tw_init<<<(NTW + 255) / 256, 256>>>();
    wround_kernel<<<(Hh * Hh) / 256, 256>>>(W);
    kf_kernel<<<NPAIR, TFFT, smem>>>(K);
    conv_kernel<<<Bb * NPAIR, TFFT, smem>>>(u, D);
    dim3 g(Ll / 128, Hh / 128, Bb);
    mix_tc_kernel<<<g, MIXT, MIX_SMEM>>>(out);
}

// round 13
// speedup vs baseline: 1.5314x; 1.0016x over previous
#include <cuda_runtime.h>
#include <cstdint>

#define Bb    8
#define Hh    512
#define Ll    8192
#define NFFT  16384
#define HALF  8192
#define QTOP  4096   /* NFFT/4 */
#define NPAIR 256    /* H/2 */
#define TFFT  512
#define NTW   5461   /* 1+4+16+...+4096 */

// ---------------- scratch (device globals; no allocation allowed) ----------------
__device__ float4 g_AB[(size_t)NPAIR * (HALF + 1)];   // per-pair spectra, pointwise iteration order
__device__ float  g_ymid[(size_t)Bb * Hh * Ll];       // conv+skip result (B,H,L), tf32-rounded
__device__ float  g_Wr[(size_t)Hh * Hh];              // W pre-rounded to tf32 (rna)
__device__ float2 g_tw1[NTW];                         // twiddle LUT per (stage,j)
__device__ float2 g_tw2[NTW];
__device__ float2 g_tw3[NTW];

// ---------------- helpers ----------------
__device__ __forceinline__ float2 cmulf(float2 a, float2 b) {
    return make_float2(a.x * b.x - a.y * b.y, a.x * b.y + a.y * b.x);
}
__device__ __forceinline__ int rev4_14(int k) {
    unsigned r = __brev((unsigned)k) >> 18;
    return (int)(((r & 0x2AAAu) >> 1) | ((r & 0x1555u) << 1));
}
__device__ __forceinline__ float tf32r(float v) {
    uint32_t r;
    asm("cvt.rna.tf32.f32 %0, %1;" : "=r"(r) : "f"(v));
    return __uint_as_float(r);
}
// bank swizzle: XOR bits[4:6) into bit-pairs [0:2) and [2:4)
__device__ __forceinline__ int sw(int n) {
    return n ^ (((n >> 4) & 3) * 5);
}
// radix-4 DFT core
__device__ __forceinline__ void bf4(float2& a0, float2& a1, float2& a2, float2& a3) {
    float t0x = a0.x + a2.x, t0y = a0.y + a2.y;
    float t1x = a0.x - a2.x, t1y = a0.y - a2.y;
    float t2x = a1.x + a3.x, t2y = a1.y + a3.y;
    float t3x = a1.x - a3.x, t3y = a1.y - a3.y;
    a0 = make_float2(t0x + t2x, t0y + t2y);
    a1 = make_float2(t1x + t3y, t1y - t3x);   // t1 - i*t3
    a2 = make_float2(t0x - t2x, t0y - t2y);
    a3 = make_float2(t1x - t3y, t1y + t3x);   // t1 + i*t3
}

// ---------------- twiddle LUT init ----------------
__global__ void tw_init() {
    int idx = blockIdx.x * 256 + threadIdx.x;
    if (idx >= NTW) return;
    int q = 1, off = 0;
    while (idx >= off + q) { off += q; q <<= 2; }
    int j = idx - off;
    int m = q << 2;
    float ang = -6.283185307179586f * ((float)j / (float)m);
    float s1, c1, s2, c2, s3, c3;
    sincosf(ang, &s1, &c1);
    sincosf(2.0f * ang, &s2, &c2);
    sincosf(3.0f * ang, &s3, &c3);
    g_tw1[idx] = make_float2(c1, s1);
    g_tw2[idx] = make_float2(c2, s2);
    g_tw3[idx] = make_float2(c3, s3);
}

// ---------------- fused load + first DIF stage (m=NFFT, top half zero) ----------------
__device__ void dif_first_fused(float2* s, const float* __restrict__ f1,
                                const float* __restrict__ f2, int tid) {
#pragma unroll 2
    for (int i = tid; i < QTOP; i += TFFT) {
        float2 a0 = make_float2(f1[i], f2[i]);
        float2 a1 = make_float2(f1[i + QTOP], f2[i + QTOP]);
        float2 b0 = make_float2(a0.x + a1.x, a0.y + a1.y);
        float2 b1 = make_float2(a0.x + a1.y, a0.y - a1.x);   // a0 - i*a1
        float2 b2 = make_float2(a0.x - a1.x, a0.y - a1.y);
        float2 b3 = make_float2(a0.x - a1.y, a0.y + a1.x);   // a0 + i*a1
        float2 w1 = __ldg(&g_tw1[1365 + i]);
        float2 w2 = __ldg(&g_tw2[1365 + i]);
        float2 w3 = __ldg(&g_tw3[1365 + i]);
        s[sw(i)]            = b0;
        s[sw(i + QTOP)]     = cmulf(b1, w1);
        s[sw(i + 2 * QTOP)] = cmulf(b2, w2);
        s[sw(i + 3 * QTOP)] = cmulf(b3, w3);
    }
    __syncthreads();
}

// ---------------- merged radix-16 DIF pass: stages (m=4Q) then (m=Q), Q4 = Q/4 ----------------
template<int Q>
__device__ __forceinline__ void dif_merged(float2* s, int tid) {
    constexpr int Q4   = Q / 4;
    constexpr int offA = (Q - 1) / 3;
    constexpr int offB = (Q4 - 1) / 3;
#pragma unroll 1
    for (int i = tid; i < NFFT / 16; i += TFFT) {
        int j  = i & (Q4 - 1);
        int g0 = (i / Q4) * (16 * Q4) + j;
        float2 x[16];
#pragma unroll
        for (int b = 0; b < 4; ++b) {
            float2 a0 = s[sw(g0 + b * Q4)];
            float2 a1 = s[sw(g0 + Q + b * Q4)];
            float2 a2 = s[sw(g0 + 2 * Q + b * Q4)];
            float2 a3 = s[sw(g0 + 3 * Q + b * Q4)];
            bf4(a0, a1, a2, a3);
            int jA = j + b * Q4;
            float2 w1 = __ldg(&g_tw1[offA + jA]);
            float2 w2 = __ldg(&g_tw2[offA + jA]);
            float2 w3 = __ldg(&g_tw3[offA + jA]);
            x[b]      = a0;
            x[4 + b]  = cmulf(a1, w1);
            x[8 + b]  = cmulf(a2, w2);
            x[12 + b] = cmulf(a3, w3);
        }
        float2 v1 = __ldg(&g_tw1[offB + j]);
        float2 v2 = __ldg(&g_tw2[offB + j]);
        float2 v3 = __ldg(&g_tw3[offB + j]);
#pragma unroll
        for (int a = 0; a < 4; ++a) {
            bf4(x[4 * a], x[4 * a + 1], x[4 * a + 2], x[4 * a + 3]);
            int n0 = g0 + a * Q;
            s[sw(n0)]           = x[4 * a];
            s[sw(n0 + Q4)]      = cmulf(x[4 * a + 1], v1);
            s[sw(n0 + 2 * Q4)]  = cmulf(x[4 * a + 2], v2);
            s[sw(n0 + 3 * Q4)]  = cmulf(x[4 * a + 3], v3);
        }
    }
    __syncthreads();
}

// ---------------- merged radix-16 DIT pass: stages (m=Q) then (m=4Q) ----------------
template<int Q>
__device__ __forceinline__ void dit_merged(float2* s, int tid) {
    constexpr int Q4   = Q / 4;
    constexpr int offA = (Q - 1) / 3;
    constexpr int offB = (Q4 - 1) / 3;
#pragma unroll 1
    for (int i = tid; i < NFFT / 16; i += TFFT) {
        int j  = i & (Q4 - 1);
        int g0 = (i / Q4) * (16 * Q4) + j;
        float2 x[16];
        float2 v1 = __ldg(&g_tw1[offB + j]);
        float2 v2 = __ldg(&g_tw2[offB + j]);
        float2 v3 = __ldg(&g_tw3[offB + j]);
#pragma unroll
        for (int a = 0; a < 4; ++a) {
            int n0 = g0 + a * Q;
            float2 c0 = s[sw(n0)];
            float2 c1 = s[sw(n0 + Q4)];
            float2 c2 = s[sw(n0 + 2 * Q4)];
            float2 c3 = s[sw(n0 + 3 * Q4)];
            c1 = cmulf(c1, v1);
            c2 = cmulf(c2, v2);
            c3 = cmulf(c3, v3);
            bf4(c0, c1, c2, c3);
            x[4 * a]     = c0;
            x[4 * a + 1] = c1;
            x[4 * a + 2] = c2;
            x[4 * a + 3] = c3;
        }
#pragma unroll
        for (int b = 0; b < 4; ++b) {
            int jA = j + b * Q4;
            float2 w1 = __ldg(&g_tw1[offA + jA]);
            float2 w2 = __ldg(&g_tw2[offA + jA]);
            float2 w3 = __ldg(&g_tw3[offA + jA]);
            float2 c0 = x[b];
            float2 c1 = cmulf(x[4 + b],  w1);
            float2 c2 = cmulf(x[8 + b],  w2);
            float2 c3 = cmulf(x[12 + b], w3);
            bf4(c0, c1, c2, c3);
            s[sw(g0 + b * Q4)]         = c0;
            s[sw(g0 + Q + b * Q4)]     = c1;
            s[sw(g0 + 2 * Q + b * Q4)] = c2;
            s[sw(g0 + 3 * Q + b * Q4)] = c3;
        }
    }
    __syncthreads();
}

// ---------------- small DIF stages m = 16, 4 ----------------
__device__ void dif_small(float2* s, int tid) {
#pragma unroll 1
    for (int m = 16; m >= 4; m >>= 2) {
        int q = m >> 2;
        int off = (q - 1) / 3;
#pragma unroll 2
        for (int i = tid; i < QTOP; i += TFFT) {
            int j = i & (q - 1);
            int base = ((i - j) << 2) + j;
            int i0 = sw(base), i1 = sw(base + q), i2 = sw(base + 2 * q), i3 = sw(base + 3 * q);
            float2 a0 = s[i0], a1 = s[i1], a2 = s[i2], a3 = s[i3];
            bf4(a0, a1, a2, a3);
            float2 w1 = __ldg(&g_tw1[off + j]);
            float2 w2 = __ldg(&g_tw2[off + j]);
            float2 w3 = __ldg(&g_tw3[off + j]);
            s[i0] = a0;
            s[i1] = cmulf(a1, w1);
            s[i2] = cmulf(a2, w2);
            s[i3] = cmulf(a3, w3);
        }
        __syncthreads();
    }
}

// ---------------- small DIT stages m = 4, 16 ----------------
__device__ void dit_small(float2* s, int tid) {
#pragma unroll 1
    for (int m = 4; m <= 16; m <<= 2) {
        int q = m >> 2;
        int off = (q - 1) / 3;
#pragma unroll 2
        for (int i = tid; i < QTOP; i += TFFT) {
            int j = i & (q - 1);
            int base = ((i - j) << 2) + j;
            int i0 = sw(base), i1 = sw(base + q), i2 = sw(base + 2 * q), i3 = sw(base + 3 * q);
            float2 c0 = s[i0], c1 = s[i1], c2 = s[i2], c3 = s[i3];
            float2 w1 = __ldg(&g_tw1[off + j]);
            float2 w2 = __ldg(&g_tw2[off + j]);
            float2 w3 = __ldg(&g_tw3[off + j]);
            c1 = cmulf(c1, w1);
            c2 = cmulf(c2, w2);
            c3 = cmulf(c3, w3);
            bf4(c0, c1, c2, c3);
            s[i0] = c0;
            s[i1] = c1;
            s[i2] = c2;
            s[i3] = c3;
        }
        __syncthreads();
    }
}

// ---------------- kernel 1: combined kernel spectra A,B per channel pair ----------------
__global__ void __launch_bounds__(TFFT, 1) kf_kernel(const float* __restrict__ K) {
    extern __shared__ float2 s[];
    int tid  = threadIdx.x;
    int pair = blockIdx.x;
    const float* k1 = K + (size_t)(2 * pair) * Ll;
    const float* k2 = K + (size_t)(2 * pair + 1) * Ll;
    dif_first_fused(s, k1, k2, tid);
    dif_merged<1024>(s, tid);
    dif_merged<64>(s, tid);
    dif_small(s, tid);

    const float inv = 1.0f / (4.0f * (float)NFFT);
    float4* AB = g_AB + (size_t)pair * (HALF + 1);
#pragma unroll 2
    for (int i = tid; i < HALF; i += TFFT) {
        int p  = ((i >> 1) << 2) | (i & 1);
        int k  = rev4_14(p);
        int kn = (NFFT - k) & (NFFT - 1);
        int p2 = rev4_14(kn);
        float2 Z  = s[sw(p)];
        float2 Zp = s[sw(p2)];
        float ax = (Z.x + Z.y + Zp.x + Zp.y) * inv;
        float ay = (Z.y - Z.x + Zp.x - Zp.y) * inv;
        float bx = (Z.x - Z.y + Zp.x - Zp.y) * inv;
        float by = (Z.x + Z.y - Zp.x - Zp.y) * inv;
        AB[i] = make_float4(ax, ay, bx, by);
    }
    if (tid == 0) {
        float2 Z = s[sw(2)];
        float ax = 2.f * (Z.x + Z.y) * inv;
        float bx = 2.f * (Z.x - Z.y) * inv;
        AB[HALF] = make_float4(ax, 0.f, bx, 0.f);
    }
}

// ---------------- kernel 2: FFT conv + skip per (batch, channel pair) ----------------
__global__ void __launch_bounds__(TFFT, 1) conv_kernel(const float* __restrict__ u,
                                                       const float* __restrict__ D) {
    extern __shared__ float2 s[];
    int tid  = threadIdx.x;
    int pair = blockIdx.x & (NPAIR - 1);
    int b    = blockIdx.x >> 8;
    int h1   = 2 * pair, h2 = h1 + 1;
    const float* u1 = u + ((size_t)b * Hh + h1) * Ll;
    const float* u2 = u + ((size_t)b * Hh + h2) * Ll;
    dif_first_fused(s, u1, u2, tid);
    dif_merged<1024>(s, tid);
    dif_merged<64>(s, tid);
    dif_small(s, tid);

    const float4* AB = g_AB + (size_t)pair * (HALF + 1);
#pragma unroll 2
    for (int i = tid; i < HALF; i += TFFT) {
        int p  = ((i >> 1) << 2) | (i & 1);
        int k  = rev4_14(p);
        int kn = (NFFT - k) & (NFFT - 1);
        int p2 = rev4_14(kn);
        int sp = sw(p), sp2 = sw(p2);
        float2 Z  = s[sp];
        float2 Zp = s[sp2];
        float4 ab = AB[i];
        float vx = Z.x * ab.x - Z.y * ab.y + Zp.x * ab.z + Zp.y * ab.w;
        float vy = Z.x * ab.y + Z.y * ab.x - Zp.y * ab.z + Zp.x * ab.w;
        s[sp] = make_float2(vx, -vy);
        if (p != 0) {
            float wx =  Zp.x * ab.x + Zp.y * ab.y + Z.x * ab.z - Z.y * ab.w;
            float wy = -Zp.x * ab.y + Zp.y * ab.x - Z.x * ab.w - Z.y * ab.z;
            s[sp2] = make_float2(wx, -wy);
        }
    }
    if (tid == 0) {
        float2 Z = s[sw(2)];
        float4 ab = AB[HALF];
        float vx = Z.x * ab.x - Z.y * ab.y + Z.x * ab.z + Z.y * ab.w;
        float vy = Z.x * ab.y + Z.y * ab.x - Z.y * ab.z + Z.x * ab.w;
        s[sw(2)] = make_float2(vx, -vy);
    }
    __syncthreads();

    dit_small(s, tid);
    dit_merged<64>(s, tid);
    dit_merged<1024>(s, tid);

    float d1 = D[h1], d2 = D[h2];
    float* y1 = g_ymid + ((size_t)b * Hh + h1) * Ll;
    float* y2 = g_ymid + ((size_t)b * Hh + h2) * Ll;
#pragma unroll 2
    for (int i = tid; i < QTOP; i += TFFT) {
        float2 c0 = s[sw(i)], c1 = s[sw(i + QTOP)], c2 = s[sw(i + 2 * QTOP)], c3 = s[sw(i + 3 * QTOP)];
        float2 w1 = __ldg(&g_tw1[1365 + i]);
        float2 w2 = __ldg(&g_tw2[1365 + i]);
        float2 w3 = __ldg(&g_tw3[1365 + i]);
        c1 = cmulf(c1, w1);
        c2 = cmulf(c2, w2);
        c3 = cmulf(c3, w3);
        float t0x = c0.x + c2.x, t0y = c0.y + c2.y;
        float t1x = c0.x - c2.x, t1y = c0.y - c2.y;
        float t2x = c1.x + c3.x, t2y = c1.y + c3.y;
        float t3x = c1.x - c3.x, t3y = c1.y - c3.y;
        float o0x = t0x + t2x, o0y = t0y + t2y;
        float o1x = t1x + t3y, o1y = t1y - t3x;
        y1[i]        = tf32r( o0x + d1 * u1[i]);
        y2[i]        = tf32r(-o0y + d2 * u2[i]);
        y1[i + QTOP] = tf32r( o1x + d1 * u1[i + QTOP]);
        y2[i + QTOP] = tf32r(-o1y + d2 * u2[i + QTOP]);
    }
}

// ---------------- kernel 2.5: pre-round W to tf32 (round-to-nearest) ----------------
__global__ void wround_kernel(const float* __restrict__ W) {
    int i = blockIdx.x * 256 + threadIdx.x;
    g_Wr[i] = tf32r(W[i]);
}

// ================= kernel 3: tf32 mma.sync mix GEMM + tanh =================
// CTA tile 128p x 128l, 4 warps (warp tile 64x64), BK=32, single sync per chunk.
#define MIXT 128
#define AS_STR 36
#define BS_STR 136
#define A_BYTES (128 * AS_STR * 4)
#define B_BYTES (32 * BS_STR * 4)
#define STAGE_BYTES (A_BYTES + B_BYTES)
#define MIX_SMEM (2 * STAGE_BYTES)

__device__ __forceinline__ void mma_tf32(float* c, const uint32_t* a, const uint32_t* b) {
    asm volatile(
        "mma.sync.aligned.m16n8k8.row.col.f32.tf32.tf32.f32 "
        "{%0,%1,%2,%3}, {%4,%5,%6,%7}, {%8,%9}, {%0,%1,%2,%3};"
        : "+f"(c[0]), "+f"(c[1]), "+f"(c[2]), "+f"(c[3])
        : "r"(a[0]), "r"(a[1]), "r"(a[2]), "r"(a[3]), "r"(b[0]), "r"(b[1]));
}
__device__ __forceinline__ void load_stage(const float* __restrict__ Wp,
                                           const float* __restrict__ Yp,
                                           uint32_t smem_stage, int c, int tid) {
    int k0 = c * 32;
#pragma unroll
    for (int i = 0; i < 8; ++i) {
        int idx = tid + i * MIXT;
        int row = idx >> 3, seg = idx & 7;
        const float* src = Wp + (size_t)row * Hh + k0 + seg * 4;
        uint32_t dst = smem_stage + (uint32_t)(row * AS_STR + seg * 4) * 4;
        asm volatile("cp.async.cg.shared.global [%0], [%1], 16;" :: "r"(dst), "l"(src));
    }
#pragma unroll
    for (int i = 0; i < 8; ++i) {
        int idx = tid + i * MIXT;
        int row = idx >> 5, seg = idx & 31;
        const float* src = Yp + (size_t)(k0 + row) * Ll + seg * 4;
        uint32_t dst = smem_stage + A_BYTES + (uint32_t)(row * BS_STR + seg * 4) * 4;
        asm volatile("cp.async.cg.shared.global [%0], [%1], 16;" :: "r"(dst), "l"(src));
    }
    asm volatile("cp.async.commit_group;" ::: "memory");
}

__global__ void __launch_bounds__(MIXT, 2) mix_tc_kernel(float* __restrict__ out) {
    extern __shared__ char smx[];
    uint32_t sb;
    asm("{ .reg .u64 t; cvta.to.shared.u64 t, %1; cvt.u32.u64 %0, t; }" : "=r"(sb) : "l"(smx));
    int tid  = threadIdx.x;
    int lane = tid & 31, wid = tid >> 5;
    int warpM = wid >> 1, warpN = wid & 1;      // 2 x 2 warps, 64x64 each
    int g = lane >> 2, tg = lane & 3;

    int b     = blockIdx.z;
    int pTile = blockIdx.y * 128;
    int lTile = blockIdx.x * 128;
    const float* Wp = g_Wr + (size_t)pTile * Hh;
    const float* Yp = g_ymid + (size_t)b * Hh * Ll + lTile;
    float* Ob = out + (size_t)b * Hh * Ll;

    float acc[4][8][4];
#pragma unroll
    for (int mt = 0; mt < 4; ++mt)
#pragma unroll
        for (int nt = 0; nt < 8; ++nt)
#pragma unroll
            for (int r = 0; r < 4; ++r) acc[mt][nt][r] = 0.f;

    load_stage(Wp, Yp, sb, 0, tid);

#pragma unroll 1
    for (int c = 0; c < Hh / 32; ++c) {
        asm volatile("cp.async.wait_group 0;" ::: "memory");
        __syncthreads();
        if (c + 1 < Hh / 32)
            load_stage(Wp, Yp, sb + ((c + 1) & 1) * STAGE_BYTES, c + 1, tid);

        const float* As = (const float*)(smx + (c & 1) * STAGE_BYTES);
        const float* Bs = (const float*)(smx + (c & 1) * STAGE_BYTES + A_BYTES);
#pragma unroll
        for (int ks = 0; ks < 4; ++ks) {
            uint32_t af[4][4], bf[8][2];
            int kc = ks * 8 + tg;
#pragma unroll
            for (int mt = 0; mt < 4; ++mt) {
                int r0 = warpM * 64 + mt * 16 + g;
                af[mt][0] = __float_as_uint(As[r0 * AS_STR + kc]);
                af[mt][1] = __float_as_uint(As[(r0 + 8) * AS_STR + kc]);
                af[mt][2] = __float_as_uint(As[r0 * AS_STR + kc + 4]);
                af[mt][3] = __float_as_uint(As[(r0 + 8) * AS_STR + kc + 4]);
            }
#pragma unroll
            for (int nt = 0; nt < 8; ++nt) {
                int l = warpN * 64 + nt * 8 + g;
                bf[nt][0] = __float_as_uint(Bs[kc * BS_STR + l]);
                bf[nt][1] = __float_as_uint(Bs[(kc + 4) * BS_STR + l]);
            }
#pragma unroll
            for (int mt = 0; mt < 4; ++mt)
#pragma unroll
                for (int nt = 0; nt < 8; ++nt)
                    mma_tf32(acc[mt][nt], af[mt], bf[nt]);
        }
    }

    // epilogue: tanh + store
#pragma unroll
    for (int mt = 0; mt < 4; ++mt) {
        int p0 = pTile + warpM * 64 + mt * 16 + g;
#pragma unroll
        for (int nt = 0; nt < 8; ++nt) {
            int l = lTile + warpN * 64 + nt * 8 + 2 * tg;
            float2 v0 = make_float2(tanhf(acc[mt][nt][0]), tanhf(acc[mt][nt][1]));
            float2 v1 = make_float2(tanhf(acc[mt][nt][2]), tanhf(acc[mt][nt][3]));
            *(float2*)(Ob + (size_t)p0 * Ll + l)       = v0;
            *(float2*)(Ob + (size_t)(p0 + 8) * Ll + l) = v1;
        }
    }
}

// ---------------- launch ----------------
extern "C" void kernel_launch(void* const* d_in, const int* in_sizes, int n_in,
                              void* d_out, int out_size) {
    const float* u = (const float*)d_in[0];
    const float* K = (const float*)d_in[1];
    const float* D = (const float*)d_in[2];
    const float* W = (const float*)d_in[3];
    float* out = (float*)d_out;

    const int smem = NFFT * (int)sizeof(float2);  // 128 KB
    cudaFuncSetAttribute(kf_kernel,   cudaFuncAttributeMaxDynamicSharedMemorySize, smem);
    cudaFuncSetAttribute(conv_kernel, cudaFuncAttributeMaxDynamicSharedMemorySize, smem);
    cudaFuncSetAttribute(mix_tc_kernel, cudaFuncAttributeMaxDynamicSharedMemorySize, MIX_SMEM);

    tw_init<<<(NTW + 255) / 256, 256>>>();
    wround_kernel<<<(Hh * Hh) / 256, 256>>>(W);
    kf_kernel<<<NPAIR, TFFT, smem>>>(K);
    conv_kernel<<<Bb * NPAIR, TFFT, smem>>>(u, D);
    dim3 g(Ll / 128, Hh / 128, Bb);
    mix_tc_kernel<<<g, MIXT, MIX_SMEM>>>(out);
}

// round 14
// speedup vs baseline: 1.5440x; 1.0082x over previous
#include <cuda_runtime.h>
#include <cstdint>

#define Bb    8
#define Hh    512
#define Ll    8192
#define NFFT  16384
#define HALF  8192
#define QTOP  4096   /* NFFT/4 */
#define NPAIR 256    /* H/2 */
#define TFFT  512
#define NTW   5461   /* 1+4+16+...+4096 */

// ---------------- scratch (device globals; no allocation allowed) ----------------
__device__ float4 g_AB[(size_t)NPAIR * (HALF + 1)];   // per-pair spectra, pointwise iteration order
__device__ float  g_ymid[(size_t)Bb * Hh * Ll];       // conv+skip result (B,H,L), tf32-rounded
__device__ float  g_Wr[(size_t)Hh * Hh];              // W pre-rounded to tf32 (rna)
__device__ float2 g_tw1[NTW];                         // twiddle LUT per (stage,j)
__device__ float2 g_tw2[NTW];
__device__ float2 g_tw3[NTW];

// ---------------- helpers ----------------
__device__ __forceinline__ float2 cmulf(float2 a, float2 b) {
    return make_float2(a.x * b.x - a.y * b.y, a.x * b.y + a.y * b.x);
}
__device__ __forceinline__ int rev4_14(int k) {
    unsigned r = __brev((unsigned)k) >> 18;
    return (int)(((r & 0x2AAAu) >> 1) | ((r & 0x1555u) << 1));
}
__device__ __forceinline__ float tf32r(float v) {
    uint32_t r;
    asm("cvt.rna.tf32.f32 %0, %1;" : "=r"(r) : "f"(v));
    return __uint_as_float(r);
}
// bank swizzle: XOR bits[4:6) into bit-pairs [0:2) and [2:4)
__device__ __forceinline__ int sw(int n) {
    return n ^ (((n >> 4) & 3) * 5);
}
// radix-4 DFT core
__device__ __forceinline__ void bf4(float2& a0, float2& a1, float2& a2, float2& a3) {
    float t0x = a0.x + a2.x, t0y = a0.y + a2.y;
    float t1x = a0.x - a2.x, t1y = a0.y - a2.y;
    float t2x = a1.x + a3.x, t2y = a1.y + a3.y;
    float t3x = a1.x - a3.x, t3y = a1.y - a3.y;
    a0 = make_float2(t0x + t2x, t0y + t2y);
    a1 = make_float2(t1x + t3y, t1y - t3x);   // t1 - i*t3
    a2 = make_float2(t0x - t2x, t0y - t2y);
    a3 = make_float2(t1x - t3y, t1y + t3x);   // t1 + i*t3
}

// ---------------- twiddle LUT init ----------------
__global__ void tw_init() {
    int idx = blockIdx.x * 256 + threadIdx.x;
    if (idx >= NTW) return;
    int q = 1, off = 0;
    while (idx >= off + q) { off += q; q <<= 2; }
    int j = idx - off;
    int m = q << 2;
    float ang = -6.283185307179586f * ((float)j / (float)m);
    float s1, c1, s2, c2, s3, c3;
    sincosf(ang, &s1, &c1);
    sincosf(2.0f * ang, &s2, &c2);
    sincosf(3.0f * ang, &s3, &c3);
    g_tw1[idx] = make_float2(c1, s1);
    g_tw2[idx] = make_float2(c2, s2);
    g_tw3[idx] = make_float2(c3, s3);
}

// ---------------- fused load + first DIF stage (m=NFFT, top half zero) ----------------
// offsets are multiples of 4096 -> bits[4:6) fixed by i -> single XOR constant.
__device__ void dif_first_fused(float2* s, const float* __restrict__ f1,
                                const float* __restrict__ f2, int tid) {
#pragma unroll 2
    for (int i = tid; i < QTOP; i += TFFT) {
        float2 a0 = make_float2(f1[i], f2[i]);
        float2 a1 = make_float2(f1[i + QTOP], f2[i + QTOP]);
        float2 b0 = make_float2(a0.x + a1.x, a0.y + a1.y);
        float2 b1 = make_float2(a0.x + a1.y, a0.y - a1.x);   // a0 - i*a1
        float2 b2 = make_float2(a0.x - a1.x, a0.y - a1.y);
        float2 b3 = make_float2(a0.x - a1.y, a0.y + a1.x);   // a0 + i*a1
        float2 w1 = __ldg(&g_tw1[1365 + i]);
        float2 w2 = __ldg(&g_tw2[1365 + i]);
        float2 w3 = __ldg(&g_tw3[1365 + i]);
        int ib = i ^ (((i >> 4) & 3) * 5);   // sw(i); offsets 4096k keep bits[4:6)
        s[ib]            = b0;
        s[ib + QTOP]     = cmulf(b1, w1);
        s[ib + 2 * QTOP] = cmulf(b2, w2);
        s[ib + 3 * QTOP] = cmulf(b3, w3);
    }
    __syncthreads();
}

// ---------------- merged radix-16 DIF pass: stages (m=4Q) then (m=Q), Q4 = Q/4 ----------------
// Q4>=64: all 16 addresses share one swizzle constant Vg (offsets multiples of 64).
// Q4==16: (g0>>4)&3 == 0, so constant is the literal 5*b / 5*d per sub-offset.
template<int Q>
__device__ __forceinline__ void dif_merged(float2* s, int tid) {
    constexpr int Q4   = Q / 4;
    constexpr int offA = (Q - 1) / 3;
    constexpr int offB = (Q4 - 1) / 3;
#pragma unroll 1
    for (int i = tid; i < NFFT / 16; i += TFFT) {
        int j  = i & (Q4 - 1);
        int g0 = (i / Q4) * (16 * Q4) + j;
        int Vg = (Q4 >= 64) ? 5 * ((g0 >> 4) & 3) : 0;
        float2 x[16];
#pragma unroll
        for (int b = 0; b < 4; ++b) {
            int ab = (g0 + b * Q4) ^ ((Q4 >= 64) ? Vg : 5 * b);
            float2 a0 = s[ab];
            float2 a1 = s[ab + Q];
            float2 a2 = s[ab + 2 * Q];
            float2 a3 = s[ab + 3 * Q];
            bf4(a0, a1, a2, a3);
            int jA = j + b * Q4;
            float2 w1 = __ldg(&g_tw1[offA + jA]);
            float2 w2 = __ldg(&g_tw2[offA + jA]);
            float2 w3 = __ldg(&g_tw3[offA + jA]);
            x[b]      = a0;
            x[4 + b]  = cmulf(a1, w1);
            x[8 + b]  = cmulf(a2, w2);
            x[12 + b] = cmulf(a3, w3);
        }
        float2 v1 = __ldg(&g_tw1[offB + j]);
        float2 v2 = __ldg(&g_tw2[offB + j]);
        float2 v3 = __ldg(&g_tw3[offB + j]);
#pragma unroll
        for (int a = 0; a < 4; ++a) {
            bf4(x[4 * a], x[4 * a + 1], x[4 * a + 2], x[4 * a + 3]);
            int n0 = g0 + a * Q;
            if (Q4 >= 64) {
                int nb = n0 ^ Vg;
                s[nb]          = x[4 * a];
                s[nb + Q4]     = cmulf(x[4 * a + 1], v1);
                s[nb + 2 * Q4] = cmulf(x[4 * a + 2], v2);
                s[nb + 3 * Q4] = cmulf(x[4 * a + 3], v3);
            } else {
                s[n0]                   = x[4 * a];
                s[(n0 + Q4) ^ 5]        = cmulf(x[4 * a + 1], v1);
                s[(n0 + 2 * Q4) ^ 10]   = cmulf(x[4 * a + 2], v2);
                s[(n0 + 3 * Q4) ^ 15]   = cmulf(x[4 * a + 3], v3);
            }
        }
    }
    __syncthreads();
}

// ---------------- merged radix-16 DIT pass: stages (m=Q) then (m=4Q) ----------------
template<int Q>
__device__ __forceinline__ void dit_merged(float2* s, int tid) {
    constexpr int Q4   = Q / 4;
    constexpr int offA = (Q - 1) / 3;
    constexpr int offB = (Q4 - 1) / 3;
#pragma unroll 1
    for (int i = tid; i < NFFT / 16; i += TFFT) {
        int j  = i & (Q4 - 1);
        int g0 = (i / Q4) * (16 * Q4) + j;
        int Vg = (Q4 >= 64) ? 5 * ((g0 >> 4) & 3) : 0;
        float2 x[16];
        float2 v1 = __ldg(&g_tw1[offB + j]);
        float2 v2 = __ldg(&g_tw2[offB + j]);
        float2 v3 = __ldg(&g_tw3[offB + j]);
#pragma unroll
        for (int a = 0; a < 4; ++a) {
            int n0 = g0 + a * Q;
            float2 c0, c1, c2, c3;
            if (Q4 >= 64) {
                int nb = n0 ^ Vg;
                c0 = s[nb];
                c1 = s[nb + Q4];
                c2 = s[nb + 2 * Q4];
                c3 = s[nb + 3 * Q4];
            } else {
                c0 = s[n0];
                c1 = s[(n0 + Q4) ^ 5];
                c2 = s[(n0 + 2 * Q4) ^ 10];
                c3 = s[(n0 + 3 * Q4) ^ 15];
            }
            c1 = cmulf(c1, v1);
            c2 = cmulf(c2, v2);
            c3 = cmulf(c3, v3);
            bf4(c0, c1, c2, c3);
            x[4 * a]     = c0;
            x[4 * a + 1] = c1;
            x[4 * a + 2] = c2;
            x[4 * a + 3] = c3;
        }
#pragma unroll
        for (int b = 0; b < 4; ++b) {
            int jA = j + b * Q4;
            float2 w1 = __ldg(&g_tw1[offA + jA]);
            float2 w2 = __ldg(&g_tw2[offA + jA]);
            float2 w3 = __ldg(&g_tw3[offA + jA]);
            float2 c0 = x[b];
            float2 c1 = cmulf(x[4 + b],  w1);
            float2 c2 = cmulf(x[8 + b],  w2);
            float2 c3 = cmulf(x[12 + b], w3);
            bf4(c0, c1, c2, c3);
            int ab = (g0 + b * Q4) ^ ((Q4 >= 64) ? Vg : 5 * b);
            s[ab]         = c0;
            s[ab + Q]     = c1;
            s[ab + 2 * Q] = c2;
            s[ab + 3 * Q] = c3;
        }
    }
    __syncthreads();
}

// ---------------- small DIF stages m = 16, 4 ----------------
__device__ void dif_small(float2* s, int tid) {
#pragma unroll 1
    for (int m = 16; m >= 4; m >>= 2) {
        int q = m >> 2;
        int off = (q - 1) / 3;
#pragma unroll 2
        for (int i = tid; i < QTOP; i += TFFT) {
            int j = i & (q - 1);
            int base = ((i - j) << 2) + j;
            int i0 = sw(base), i1 = sw(base + q), i2 = sw(base + 2 * q), i3 = sw(base + 3 * q);
            float2 a0 = s[i0], a1 = s[i1], a2 = s[i2], a3 = s[i3];
            bf4(a0, a1, a2, a3);
            float2 w1 = __ldg(&g_tw1[off + j]);
            float2 w2 = __ldg(&g_tw2[off + j]);
            float2 w3 = __ldg(&g_tw3[off + j]);
            s[i0] = a0;
            s[i1] = cmulf(a1, w1);
            s[i2] = cmulf(a2, w2);
            s[i3] = cmulf(a3, w3);
        }
        __syncthreads();
    }
}

// ---------------- small DIT stages m = 4, 16 ----------------
__device__ void dit_small(float2* s, int tid) {
#pragma unroll 1
    for (int m = 4; m <= 16; m <<= 2) {
        int q = m >> 2;
        int off = (q - 1) / 3;
#pragma unroll 2
        for (int i = tid; i < QTOP; i += TFFT) {
            int j = i & (q - 1);
            int base = ((i - j) << 2) + j;
            int i0 = sw(base), i1 = sw(base + q), i2 = sw(base + 2 * q), i3 = sw(base + 3 * q);
            float2 c0 = s[i0], c1 = s[i1], c2 = s[i2], c3 = s[i3];
            float2 w1 = __ldg(&g_tw1[off + j]);
            float2 w2 = __ldg(&g_tw2[off + j]);
            float2 w3 = __ldg(&g_tw3[off + j]);
            c1 = cmulf(c1, w1);
            c2 = cmulf(c2, w2);
            c3 = cmulf(c3, w3);
            bf4(c0, c1, c2, c3);
            s[i0] = c0;
            s[i1] = c1;
            s[i2] = c2;
            s[i3] = c3;
        }
        __syncthreads();
    }
}

// ---------------- kernel 1: combined kernel spectra A,B per channel pair ----------------
__global__ void __launch_bounds__(TFFT, 1) kf_kernel(const float* __restrict__ K) {
    extern __shared__ float2 s[];
    int tid  = threadIdx.x;
    int pair = blockIdx.x;
    const float* k1 = K + (size_t)(2 * pair) * Ll;
    const float* k2 = K + (size_t)(2 * pair + 1) * Ll;
    dif_first_fused(s, k1, k2, tid);
    dif_merged<1024>(s, tid);
    dif_merged<64>(s, tid);
    dif_small(s, tid);

    const float inv = 1.0f / (4.0f * (float)NFFT);
    float4* AB = g_AB + (size_t)pair * (HALF + 1);
#pragma unroll 2
    for (int i = tid; i < HALF; i += TFFT) {
        int p  = ((i >> 1) << 2) | (i & 1);
        int k  = rev4_14(p);
        int kn = (NFFT - k) & (NFFT - 1);
        int p2 = rev4_14(kn);
        float2 Z  = s[sw(p)];
        float2 Zp = s[sw(p2)];
        float ax = (Z.x + Z.y + Zp.x + Zp.y) * inv;
        float ay = (Z.y - Z.x + Zp.x - Zp.y) * inv;
        float bx = (Z.x - Z.y + Zp.x - Zp.y) * inv;
        float by = (Z.x + Z.y - Zp.x - Zp.y) * inv;
        AB[i] = make_float4(ax, ay, bx, by);
    }
    if (tid == 0) {
        float2 Z = s[sw(2)];
        float ax = 2.f * (Z.x + Z.y) * inv;
        float bx = 2.f * (Z.x - Z.y) * inv;
        AB[HALF] = make_float4(ax, 0.f, bx, 0.f);
    }
}

// ---------------- kernel 2: FFT conv + skip per (batch, channel pair) ----------------
__global__ void __launch_bounds__(TFFT, 1) conv_kernel(const float* __restrict__ u,
                                                       const float* __restrict__ D) {
    extern __shared__ float2 s[];
    int tid  = threadIdx.x;
    int pair = blockIdx.x & (NPAIR - 1);
    int b    = blockIdx.x >> 8;
    int h1   = 2 * pair, h2 = h1 + 1;
    const float* u1 = u + ((size_t)b * Hh + h1) * Ll;
    const float* u2 = u + ((size_t)b * Hh + h2) * Ll;
    dif_first_fused(s, u1, u2, tid);
    dif_merged<1024>(s, tid);
    dif_merged<64>(s, tid);
    dif_small(s, tid);

    const float4* AB = g_AB + (size_t)pair * (HALF + 1);
#pragma unroll 2
    for (int i = tid; i < HALF; i += TFFT) {
        int p  = ((i >> 1) << 2) | (i & 1);
        int k  = rev4_14(p);
        int kn = (NFFT - k) & (NFFT - 1);
        int p2 = rev4_14(kn);
        int sp = sw(p), sp2 = sw(p2);
        float2 Z  = s[sp];
        float2 Zp = s[sp2];
        float4 ab = AB[i];
        float vx = Z.x * ab.x - Z.y * ab.y + Zp.x * ab.z + Zp.y * ab.w;
        float vy = Z.x * ab.y + Z.y * ab.x - Zp.y * ab.z + Zp.x * ab.w;
        s[sp] = make_float2(vx, -vy);
        if (p != 0) {
            float wx =  Zp.x * ab.x + Zp.y * ab.y + Z.x * ab.z - Z.y * ab.w;
            float wy = -Zp.x * ab.y + Zp.y * ab.x - Z.x * ab.w - Z.y * ab.z;
            s[sp2] = make_float2(wx, -wy);
        }
    }
    if (tid == 0) {
        float2 Z = s[sw(2)];
        float4 ab = AB[HALF];
        float vx = Z.x * ab.x - Z.y * ab.y + Z.x * ab.z + Z.y * ab.w;
        float vy = Z.x * ab.y + Z.y * ab.x - Z.y * ab.z + Z.x * ab.w;
        s[sw(2)] = make_float2(vx, -vy);
    }
    __syncthreads();

    dit_small(s, tid);
    dit_merged<64>(s, tid);
    dit_merged<1024>(s, tid);

    float d1 = D[h1], d2 = D[h2];
    float* y1 = g_ymid + ((size_t)b * Hh + h1) * Ll;
    float* y2 = g_ymid + ((size_t)b * Hh + h2) * Ll;
#pragma unroll 2
    for (int i = tid; i < QTOP; i += TFFT) {
        int ib = i ^ (((i >> 4) & 3) * 5);   // sw(i); offsets 4096k share it
        float2 c0 = s[ib], c1 = s[ib + QTOP], c2 = s[ib + 2 * QTOP], c3 = s[ib + 3 * QTOP];
        float2 w1 = __ldg(&g_tw1[1365 + i]);
        float2 w2 = __ldg(&g_tw2[1365 + i]);
        float2 w3 = __ldg(&g_tw3[1365 + i]);
        c1 = cmulf(c1, w1);
        c2 = cmulf(c2, w2);
        c3 = cmulf(c3, w3);
        float t0x = c0.x + c2.x, t0y = c0.y + c2.y;
        float t1x = c0.x - c2.x, t1y = c0.y - c2.y;
        float t2x = c1.x + c3.x, t2y = c1.y + c3.y;
        float t3x = c1.x - c3.x, t3y = c1.y - c3.y;
        float o0x = t0x + t2x, o0y = t0y + t2y;
        float o1x = t1x + t3y, o1y = t1y - t3x;
        y1[i]        = tf32r( o0x + d1 * u1[i]);
        y2[i]        = tf32r(-o0y + d2 * u2[i]);
        y1[i + QTOP] = tf32r( o1x + d1 * u1[i + QTOP]);
        y2[i + QTOP] = tf32r(-o1y + d2 * u2[i + QTOP]);
    }
}

// ---------------- kernel 2.5: pre-round W to tf32 (round-to-nearest) ----------------
__global__ void wround_kernel(const float* __restrict__ W) {
    int i = blockIdx.x * 256 + threadIdx.x;
    g_Wr[i] = tf32r(W[i]);
}

// ================= kernel 3: tf32 mma.sync mix GEMM + tanh =================
// CTA tile 128p x 128l, 4 warps (warp tile 64x64), BK=32, single sync per chunk.
#define MIXT 128
#define AS_STR 36
#define BS_STR 136
#define A_BYTES (128 * AS_STR * 4)
#define B_BYTES (32 * BS_STR * 4)
#define STAGE_BYTES (A_BYTES + B_BYTES)
#define MIX_SMEM (2 * STAGE_BYTES)

__device__ __forceinline__ void mma_tf32(float* c, const uint32_t* a, const uint32_t* b) {
    asm volatile(
        "mma.sync.aligned.m16n8k8.row.col.f32.tf32.tf32.f32 "
        "{%0,%1,%2,%3}, {%4,%5,%6,%7}, {%8,%9}, {%0,%1,%2,%3};"
        : "+f"(c[0]), "+f"(c[1]), "+f"(c[2]), "+f"(c[3])
        : "r"(a[0]), "r"(a[1]), "r"(a[2]), "r"(a[3]), "r"(b[0]), "r"(b[1]));
}
__device__ __forceinline__ void load_stage(const float* __restrict__ Wp,
                                           const float* __restrict__ Yp,
                                           uint32_t smem_stage, int c, int tid) {
    int k0 = c * 32;
#pragma unroll
    for (int i = 0; i < 8; ++i) {
        int idx = tid + i * MIXT;
        int row = idx >> 3, seg = idx & 7;
        const float* src = Wp + (size_t)row * Hh + k0 + seg * 4;
        uint32_t dst = smem_stage + (uint32_t)(row * AS_STR + seg * 4) * 4;
        asm volatile("cp.async.cg.shared.global [%0], [%1], 16;" :: "r"(dst), "l"(src));
    }
#pragma unroll
    for (int i = 0; i < 8; ++i) {
        int idx = tid + i * MIXT;
        int row = idx >> 5, seg = idx & 31;
        const float* src = Yp + (size_t)(k0 + row) * Ll + seg * 4;
        uint32_t dst = smem_stage + A_BYTES + (uint32_t)(row * BS_STR + seg * 4) * 4;
        asm volatile("cp.async.cg.shared.global [%0], [%1], 16;" :: "r"(dst), "l"(src));
    }
    asm volatile("cp.async.commit_group;" ::: "memory");
}

__global__ void __launch_bounds__(MIXT, 2) mix_tc_kernel(float* __restrict__ out) {
    extern __shared__ char smx[];
    uint32_t sb;
    asm("{ .reg .u64 t; cvta.to.shared.u64 t, %1; cvt.u32.u64 %0, t; }" : "=r"(sb) : "l"(smx));
    int tid  = threadIdx.x;
    int lane = tid & 31, wid = tid >> 5;
    int warpM = wid >> 1, warpN = wid & 1;      // 2 x 2 warps, 64x64 each
    int g = lane >> 2, tg = lane & 3;

    int b     = blockIdx.z;
    int pTile = blockIdx.y * 128;
    int lTile = blockIdx.x * 128;
    const float* Wp = g_Wr + (size_t)pTile * Hh;
    const float* Yp = g_ymid + (size_t)b * Hh * Ll + lTile;
    float* Ob = out + (size_t)b * Hh * Ll;

    float acc[4][8][4];
#pragma unroll
    for (int mt = 0; mt < 4; ++mt)
#pragma unroll
        for (int nt = 0; nt < 8; ++nt)
#pragma unroll
            for (int r = 0; r < 4; ++r) acc[mt][nt][r] = 0.f;

    load_stage(Wp, Yp, sb, 0, tid);

#pragma unroll 1
    for (int c = 0; c < Hh / 32; ++c) {
        asm volatile("cp.async.wait_group 0;" ::: "memory");
        __syncthreads();
        if (c + 1 < Hh / 32)
            load_stage(Wp, Yp, sb + ((c + 1) & 1) * STAGE_BYTES, c + 1, tid);

        const float* As = (const float*)(smx + (c & 1) * STAGE_BYTES);
        const float* Bs = (const float*)(smx + (c & 1) * STAGE_BYTES + A_BYTES);
#pragma unroll
        for (int ks = 0; ks < 4; ++ks) {
            uint32_t af[4][4], bf[8][2];
            int kc = ks * 8 + tg;
#pragma unroll
            for (int mt = 0; mt < 4; ++mt) {
                int r0 = warpM * 64 + mt * 16 + g;
                af[mt][0] = __float_as_uint(As[r0 * AS_STR + kc]);
                af[mt][1] = __float_as_uint(As[(r0 + 8) * AS_STR + kc]);
                af[mt][2] = __float_as_uint(As[r0 * AS_STR + kc + 4]);
                af[mt][3] = __float_as_uint(As[(r0 + 8) * AS_STR + kc + 4]);
            }
#pragma unroll
            for (int nt = 0; nt < 8; ++nt) {
                int l = warpN * 64 + nt * 8 + g;
                bf[nt][0] = __float_as_uint(Bs[kc * BS_STR + l]);
                bf[nt][1] = __float_as_uint(Bs[(kc + 4) * BS_STR + l]);
            }
#pragma unroll
            for (int mt = 0; mt < 4; ++mt)
#pragma unroll
                for (int nt = 0; nt < 8; ++nt)
                    mma_tf32(acc[mt][nt], af[mt], bf[nt]);
        }
    }

    // epilogue: tanh + store
#pragma unroll
    for (int mt = 0; mt < 4; ++mt) {
        int p0 = pTile + warpM * 64 + mt * 16 + g;
#pragma unroll
        for (int nt = 0; nt < 8; ++nt) {
            int l = lTile + warpN * 64 + nt * 8 + 2 * tg;
            float2 v0 = make_float2(tanhf(acc[mt][nt][0]), tanhf(acc[mt][nt][1]));
            float2 v1 = make_float2(tanhf(acc[mt][nt][2]), tanhf(acc[mt][nt][3]));
            *(float2*)(Ob + (size_t)p0 * Ll + l)       = v0;
            *(float2*)(Ob + (size_t)(p0 + 8) * Ll + l) = v1;
        }
    }
}

// ---------------- launch ----------------
extern "C" void kernel_launch(void* const* d_in, const int* in_sizes, int n_in,
                              void* d_out, int out_size) {
    const float* u = (const float*)d_in[0];
    const float* K = (const float*)d_in[1];
    const float* D = (const float*)d_in[2];
    const float* W = (const float*)d_in[3];
    float* out = (float*)d_out;

    const int smem = NFFT * (int)sizeof(float2);  // 128 KB
    cudaFuncSetAttribute(kf_kernel,   cudaFuncAttributeMaxDynamicSharedMemorySize, smem);
    cudaFuncSetAttribute(conv_kernel, cudaFuncAttributeMaxDynamicSharedMemorySize, smem);
    cudaFuncSetAttribute(mix_tc_kernel, cudaFuncAttributeMaxDynamicSharedMemorySize, MIX_SMEM);

    tw_init<<<(NTW + 255) / 256, 256>>>();
    wround_kernel<<<(Hh * Hh) / 256, 256>>>(W);
    kf_kernel<<<NPAIR, TFFT, smem>>>(K);
    conv_kernel<<<Bb * NPAIR, TFFT, smem>>>(u, D);
    dim3 g(Ll / 128, Hh / 128, Bb);
    mix_tc_kernel<<<g, MIXT, MIX_SMEM>>>(out);
}

// round 15
// speedup vs baseline: 1.6354x; 1.0592x over previous
#include <cuda_runtime.h>
#include <cstdint>

#define Bb    8
#define Hh    512
#define Ll    8192
#define NFFT  16384
#define HALF  8192
#define QTOP  4096   /* NFFT/4 */
#define NPAIR 256    /* H/2 */
#define TFFT  512
#define NTW   5461   /* 1+4+16+...+4096 */

// ---------------- scratch (device globals; no allocation allowed) ----------------
__device__ float4 g_AB[(size_t)NPAIR * (HALF + 1)];   // per-pair spectra, pointwise iteration order
__device__ float  g_ymid[(size_t)Bb * Hh * Ll];       // conv+skip result (B,H,L), tf32-rounded
__device__ float  g_Wr[(size_t)Hh * Hh];              // W pre-rounded to tf32 (rna)
__device__ float2 g_tw1[NTW];                         // twiddle LUT per (stage,j)
__device__ float2 g_tw2[NTW];
__device__ float2 g_tw3[NTW];

// ---------------- helpers ----------------
__device__ __forceinline__ float2 cmulf(float2 a, float2 b) {
    return make_float2(a.x * b.x - a.y * b.y, a.x * b.y + a.y * b.x);
}
__device__ __forceinline__ int rev4_14(int k) {
    unsigned r = __brev((unsigned)k) >> 18;
    return (int)(((r & 0x2AAAu) >> 1) | ((r & 0x1555u) << 1));
}
__device__ __forceinline__ float tf32r(float v) {
    uint32_t r;
    asm("cvt.rna.tf32.f32 %0, %1;" : "=r"(r) : "f"(v));
    return __uint_as_float(r);
}
// bank swizzle: XOR bits[4:6) into bit-pairs [0:2) and [2:4)
__device__ __forceinline__ int sw(int n) {
    return n ^ (((n >> 4) & 3) * 5);
}
// radix-4 DFT core
__device__ __forceinline__ void bf4(float2& a0, float2& a1, float2& a2, float2& a3) {
    float t0x = a0.x + a2.x, t0y = a0.y + a2.y;
    float t1x = a0.x - a2.x, t1y = a0.y - a2.y;
    float t2x = a1.x + a3.x, t2y = a1.y + a3.y;
    float t3x = a1.x - a3.x, t3y = a1.y - a3.y;
    a0 = make_float2(t0x + t2x, t0y + t2y);
    a1 = make_float2(t1x + t3y, t1y - t3x);   // t1 - i*t3
    a2 = make_float2(t0x - t2x, t0y - t2y);
    a3 = make_float2(t1x - t3y, t1y + t3x);   // t1 + i*t3
}

// ---------------- twiddle LUT init ----------------
__global__ void tw_init() {
    int idx = blockIdx.x * 256 + threadIdx.x;
    if (idx >= NTW) return;
    int q = 1, off = 0;
    while (idx >= off + q) { off += q; q <<= 2; }
    int j = idx - off;
    int m = q << 2;
    float ang = -6.283185307179586f * ((float)j / (float)m);
    float s1, c1, s2, c2, s3, c3;
    sincosf(ang, &s1, &c1);
    sincosf(2.0f * ang, &s2, &c2);
    sincosf(3.0f * ang, &s3, &c3);
    g_tw1[idx] = make_float2(c1, s1);
    g_tw2[idx] = make_float2(c2, s2);
    g_tw3[idx] = make_float2(c3, s3);
}

// ---------------- fused load + first DIF stage (m=NFFT, top half zero) ----------------
__device__ void dif_first_fused(float2* s, const float* __restrict__ f1,
                                const float* __restrict__ f2, int tid) {
#pragma unroll 4
    for (int i = tid; i < QTOP; i += TFFT) {
        float2 a0 = make_float2(f1[i], f2[i]);
        float2 a1 = make_float2(f1[i + QTOP], f2[i + QTOP]);
        float2 b0 = make_float2(a0.x + a1.x, a0.y + a1.y);
        float2 b1 = make_float2(a0.x + a1.y, a0.y - a1.x);   // a0 - i*a1
        float2 b2 = make_float2(a0.x - a1.x, a0.y - a1.y);
        float2 b3 = make_float2(a0.x - a1.y, a0.y + a1.x);   // a0 + i*a1
        float2 w1 = __ldg(&g_tw1[1365 + i]);
        float2 w2 = __ldg(&g_tw2[1365 + i]);
        float2 w3 = __ldg(&g_tw3[1365 + i]);
        int ib = i ^ (((i >> 4) & 3) * 5);   // sw(i); offsets 4096k keep bits[4:6)
        s[ib]            = b0;
        s[ib + QTOP]     = cmulf(b1, w1);
        s[ib + 2 * QTOP] = cmulf(b2, w2);
        s[ib + 3 * QTOP] = cmulf(b3, w3);
    }
    __syncthreads();
}

// ---------------- merged radix-16 DIF pass: stages (m=4Q) then (m=Q), Q4 = Q/4 ----------------
template<int Q>
__device__ __forceinline__ void dif_merged(float2* s, int tid) {
    constexpr int Q4   = Q / 4;
    constexpr int offA = (Q - 1) / 3;
    constexpr int offB = (Q4 - 1) / 3;
#pragma unroll 1
    for (int i = tid; i < NFFT / 16; i += TFFT) {
        int j  = i & (Q4 - 1);
        int g0 = (i / Q4) * (16 * Q4) + j;
        int Vg = (Q4 >= 64) ? 5 * ((g0 >> 4) & 3) : 0;
        float2 x[16];
#pragma unroll
        for (int b = 0; b < 4; ++b) {
            int ab = (g0 + b * Q4) ^ ((Q4 >= 64) ? Vg : 5 * b);
            float2 a0 = s[ab];
            float2 a1 = s[ab + Q];
            float2 a2 = s[ab + 2 * Q];
            float2 a3 = s[ab + 3 * Q];
            bf4(a0, a1, a2, a3);
            int jA = j + b * Q4;
            float2 w1 = __ldg(&g_tw1[offA + jA]);
            float2 w2 = __ldg(&g_tw2[offA + jA]);
            float2 w3 = __ldg(&g_tw3[offA + jA]);
            x[b]      = a0;
            x[4 + b]  = cmulf(a1, w1);
            x[8 + b]  = cmulf(a2, w2);
            x[12 + b] = cmulf(a3, w3);
        }
        float2 v1 = __ldg(&g_tw1[offB + j]);
        float2 v2 = __ldg(&g_tw2[offB + j]);
        float2 v3 = __ldg(&g_tw3[offB + j]);
#pragma unroll
        for (int a = 0; a < 4; ++a) {
            bf4(x[4 * a], x[4 * a + 1], x[4 * a + 2], x[4 * a + 3]);
            int n0 = g0 + a * Q;
            if (Q4 >= 64) {
                int nb = n0 ^ Vg;
                s[nb]          = x[4 * a];
                s[nb + Q4]     = cmulf(x[4 * a + 1], v1);
                s[nb + 2 * Q4] = cmulf(x[4 * a + 2], v2);
                s[nb + 3 * Q4] = cmulf(x[4 * a + 3], v3);
            } else {
                s[n0]                   = x[4 * a];
                s[(n0 + Q4) ^ 5]        = cmulf(x[4 * a + 1], v1);
                s[(n0 + 2 * Q4) ^ 10]   = cmulf(x[4 * a + 2], v2);
                s[(n0 + 3 * Q4) ^ 15]   = cmulf(x[4 * a + 3], v3);
            }
        }
    }
    __syncthreads();
}

// ---------------- merged radix-16 DIT pass: stages (m=Q) then (m=4Q) ----------------
template<int Q>
__device__ __forceinline__ void dit_merged(float2* s, int tid) {
    constexpr int Q4   = Q / 4;
    constexpr int offA = (Q - 1) / 3;
    constexpr int offB = (Q4 - 1) / 3;
#pragma unroll 1
    for (int i = tid; i < NFFT / 16; i += TFFT) {
        int j  = i & (Q4 - 1);
        int g0 = (i / Q4) * (16 * Q4) + j;
        int Vg = (Q4 >= 64) ? 5 * ((g0 >> 4) & 3) : 0;
        float2 x[16];
        float2 v1 = __ldg(&g_tw1[offB + j]);
        float2 v2 = __ldg(&g_tw2[offB + j]);
        float2 v3 = __ldg(&g_tw3[offB + j]);
#pragma unroll
        for (int a = 0; a < 4; ++a) {
            int n0 = g0 + a * Q;
            float2 c0, c1, c2, c3;
            if (Q4 >= 64) {
                int nb = n0 ^ Vg;
                c0 = s[nb];
                c1 = s[nb + Q4];
                c2 = s[nb + 2 * Q4];
                c3 = s[nb + 3 * Q4];
            } else {
                c0 = s[n0];
                c1 = s[(n0 + Q4) ^ 5];
                c2 = s[(n0 + 2 * Q4) ^ 10];
                c3 = s[(n0 + 3 * Q4) ^ 15];
            }
            c1 = cmulf(c1, v1);
            c2 = cmulf(c2, v2);
            c3 = cmulf(c3, v3);
            bf4(c0, c1, c2, c3);
            x[4 * a]     = c0;
            x[4 * a + 1] = c1;
            x[4 * a + 2] = c2;
            x[4 * a + 3] = c3;
        }
#pragma unroll
        for (int b = 0; b < 4; ++b) {
            int jA = j + b * Q4;
            float2 w1 = __ldg(&g_tw1[offA + jA]);
            float2 w2 = __ldg(&g_tw2[offA + jA]);
            float2 w3 = __ldg(&g_tw3[offA + jA]);
            float2 c0 = x[b];
            float2 c1 = cmulf(x[4 + b],  w1);
            float2 c2 = cmulf(x[8 + b],  w2);
            float2 c3 = cmulf(x[12 + b], w3);
            bf4(c0, c1, c2, c3);
            int ab = (g0 + b * Q4) ^ ((Q4 >= 64) ? Vg : 5 * b);
            s[ab]         = c0;
            s[ab + Q]     = c1;
            s[ab + 2 * Q] = c2;
            s[ab + 3 * Q] = c3;
        }
    }
    __syncthreads();
}

// ---------------- small DIF stages m = 16, 4 ----------------
__device__ void dif_small(float2* s, int tid) {
#pragma unroll 1
    for (int m = 16; m >= 4; m >>= 2) {
        int q = m >> 2;
        int off = (q - 1) / 3;
#pragma unroll 4
        for (int i = tid; i < QTOP; i += TFFT) {
            int j = i & (q - 1);
            int base = ((i - j) << 2) + j;
            int i0 = sw(base), i1 = sw(base + q), i2 = sw(base + 2 * q), i3 = sw(base + 3 * q);
            float2 a0 = s[i0], a1 = s[i1], a2 = s[i2], a3 = s[i3];
            bf4(a0, a1, a2, a3);
            float2 w1 = __ldg(&g_tw1[off + j]);
            float2 w2 = __ldg(&g_tw2[off + j]);
            float2 w3 = __ldg(&g_tw3[off + j]);
            s[i0] = a0;
            s[i1] = cmulf(a1, w1);
            s[i2] = cmulf(a2, w2);
            s[i3] = cmulf(a3, w3);
        }
        __syncthreads();
    }
}

// ---------------- small DIT stages m = 4, 16 ----------------
__device__ void dit_small(float2* s, int tid) {
#pragma unroll 1
    for (int m = 4; m <= 16; m <<= 2) {
        int q = m >> 2;
        int off = (q - 1) / 3;
#pragma unroll 4
        for (int i = tid; i < QTOP; i += TFFT) {
            int j = i & (q - 1);
            int base = ((i - j) << 2) + j;
            int i0 = sw(base), i1 = sw(base + q), i2 = sw(base + 2 * q), i3 = sw(base + 3 * q);
            float2 c0 = s[i0], c1 = s[i1], c2 = s[i2], c3 = s[i3];
            float2 w1 = __ldg(&g_tw1[off + j]);
            float2 w2 = __ldg(&g_tw2[off + j]);
            float2 w3 = __ldg(&g_tw3[off + j]);
            c1 = cmulf(c1, w1);
            c2 = cmulf(c2, w2);
            c3 = cmulf(c3, w3);
            bf4(c0, c1, c2, c3);
            s[i0] = c0;
            s[i1] = c1;
            s[i2] = c2;
            s[i3] = c3;
        }
        __syncthreads();
    }
}

// ---------------- kernel 1: combined kernel spectra A,B per channel pair ----------------
__global__ void __launch_bounds__(TFFT, 1) kf_kernel(const float* __restrict__ K) {
    extern __shared__ float2 s[];
    int tid  = threadIdx.x;
    int pair = blockIdx.x;
    const float* k1 = K + (size_t)(2 * pair) * Ll;
    const float* k2 = K + (size_t)(2 * pair + 1) * Ll;
    dif_first_fused(s, k1, k2, tid);
    dif_merged<1024>(s, tid);
    dif_merged<64>(s, tid);
    dif_small(s, tid);

    const float inv = 1.0f / (4.0f * (float)NFFT);
    float4* AB = g_AB + (size_t)pair * (HALF + 1);
#pragma unroll 4
    for (int i = tid; i < HALF; i += TFFT) {
        int p  = ((i >> 1) << 2) | (i & 1);
        int k  = rev4_14(p);
        int kn = (NFFT - k) & (NFFT - 1);
        int p2 = rev4_14(kn);
        float2 Z  = s[sw(p)];
        float2 Zp = s[sw(p2)];
        float ax = (Z.x + Z.y + Zp.x + Zp.y) * inv;
        float ay = (Z.y - Z.x + Zp.x - Zp.y) * inv;
        float bx = (Z.x - Z.y + Zp.x - Zp.y) * inv;
        float by = (Z.x + Z.y - Zp.x - Zp.y) * inv;
        AB[i] = make_float4(ax, ay, bx, by);
    }
    if (tid == 0) {
        float2 Z = s[sw(2)];
        float ax = 2.f * (Z.x + Z.y) * inv;
        float bx = 2.f * (Z.x - Z.y) * inv;
        AB[HALF] = make_float4(ax, 0.f, bx, 0.f);
    }
}

// ---------------- kernel 2: FFT conv + skip per (batch, channel pair) ----------------
__global__ void __launch_bounds__(TFFT, 1) conv_kernel(const float* __restrict__ u,
                                                       const float* __restrict__ D) {
    extern __shared__ float2 s[];
    int tid  = threadIdx.x;
    int pair = blockIdx.x & (NPAIR - 1);
    int b    = blockIdx.x >> 8;
    int h1   = 2 * pair, h2 = h1 + 1;
    const float* u1 = u + ((size_t)b * Hh + h1) * Ll;
    const float* u2 = u + ((size_t)b * Hh + h2) * Ll;
    dif_first_fused(s, u1, u2, tid);
    dif_merged<1024>(s, tid);
    dif_merged<64>(s, tid);
    dif_small(s, tid);

    const float4* AB = g_AB + (size_t)pair * (HALF + 1);
#pragma unroll 4
    for (int i = tid; i < HALF; i += TFFT) {
        int p  = ((i >> 1) << 2) | (i & 1);
        int k  = rev4_14(p);
        int kn = (NFFT - k) & (NFFT - 1);
        int p2 = rev4_14(kn);
        int sp = sw(p), sp2 = sw(p2);
        float2 Z  = s[sp];
        float2 Zp = s[sp2];
        float4 ab = AB[i];
        float vx = Z.x * ab.x - Z.y * ab.y + Zp.x * ab.z + Zp.y * ab.w;
        float vy = Z.x * ab.y + Z.y * ab.x - Zp.y * ab.z + Zp.x * ab.w;
        s[sp] = make_float2(vx, -vy);
        if (p != 0) {
            float wx =  Zp.x * ab.x + Zp.y * ab.y + Z.x * ab.z - Z.y * ab.w;
            float wy = -Zp.x * ab.y + Zp.y * ab.x - Z.x * ab.w - Z.y * ab.z;
            s[sp2] = make_float2(wx, -wy);
        }
    }
    if (tid == 0) {
        float2 Z = s[sw(2)];
        float4 ab = AB[HALF];
        float vx = Z.x * ab.x - Z.y * ab.y + Z.x * ab.z + Z.y * ab.w;
        float vy = Z.x * ab.y + Z.y * ab.x - Z.y * ab.z + Z.x * ab.w;
        s[sw(2)] = make_float2(vx, -vy);
    }
    __syncthreads();

    dit_small(s, tid);
    dit_merged<64>(s, tid);
    dit_merged<1024>(s, tid);

    float d1 = D[h1], d2 = D[h2];
    float* y1 = g_ymid + ((size_t)b * Hh + h1) * Ll;
    float* y2 = g_ymid + ((size_t)b * Hh + h2) * Ll;
#pragma unroll 4
    for (int i = tid; i < QTOP; i += TFFT) {
        int ib = i ^ (((i >> 4) & 3) * 5);   // sw(i); offsets 4096k share it
        float2 c0 = s[ib], c1 = s[ib + QTOP], c2 = s[ib + 2 * QTOP], c3 = s[ib + 3 * QTOP];
        float2 w1 = __ldg(&g_tw1[1365 + i]);
        float2 w2 = __ldg(&g_tw2[1365 + i]);
        float2 w3 = __ldg(&g_tw3[1365 + i]);
        c1 = cmulf(c1, w1);
        c2 = cmulf(c2, w2);
        c3 = cmulf(c3, w3);
        float t0x = c0.x + c2.x, t0y = c0.y + c2.y;
        float t1x = c0.x - c2.x, t1y = c0.y - c2.y;
        float t2x = c1.x + c3.x, t2y = c1.y + c3.y;
        float t3x = c1.x - c3.x, t3y = c1.y - c3.y;
        float o0x = t0x + t2x, o0y = t0y + t2y;
        float o1x = t1x + t3y, o1y = t1y - t3x;
        y1[i]        = tf32r( o0x + d1 * u1[i]);
        y2[i]        = tf32r(-o0y + d2 * u2[i]);
        y1[i + QTOP] = tf32r( o1x + d1 * u1[i + QTOP]);
        y2[i + QTOP] = tf32r(-o1y + d2 * u2[i + QTOP]);
    }
}

// ---------------- kernel 2.5: pre-round W to tf32 (round-to-nearest) ----------------
__global__ void wround_kernel(const float* __restrict__ W) {
    int i = blockIdx.x * 256 + threadIdx.x;
    g_Wr[i] = tf32r(W[i]);
}

// ================= kernel 3: tf32 mma.sync mix GEMM + tanh =================
// CTA tile 128p x 128l, 4 warps (warp tile 64x64), BK=32, 3-stage cp.async pipeline.
#define MIXT 128
#define NCHK (Hh / 32)                 /* 16 */
#define AS_STR 36
#define BS_STR 136
#define A_BYTES (128 * AS_STR * 4)
#define B_BYTES (32 * BS_STR * 4)
#define STAGE_BYTES (A_BYTES + B_BYTES)
#define MIX_SMEM (3 * STAGE_BYTES)     /* 107520 */

__device__ __forceinline__ void mma_tf32(float* c, const uint32_t* a, const uint32_t* b) {
    asm volatile(
        "mma.sync.aligned.m16n8k8.row.col.f32.tf32.tf32.f32 "
        "{%0,%1,%2,%3}, {%4,%5,%6,%7}, {%8,%9}, {%0,%1,%2,%3};"
        : "+f"(c[0]), "+f"(c[1]), "+f"(c[2]), "+f"(c[3])
        : "r"(a[0]), "r"(a[1]), "r"(a[2]), "r"(a[3]), "r"(b[0]), "r"(b[1]));
}
__device__ __forceinline__ void load_stage(const float* __restrict__ Wp,
                                           const float* __restrict__ Yp,
                                           uint32_t smem_stage, int c, int tid) {
    int k0 = c * 32;
#pragma unroll
    for (int i = 0; i < 8; ++i) {
        int idx = tid + i * MIXT;
        int row = idx >> 3, seg = idx & 7;
        const float* src = Wp + (size_t)row * Hh + k0 + seg * 4;
        uint32_t dst = smem_stage + (uint32_t)(row * AS_STR + seg * 4) * 4;
        asm volatile("cp.async.cg.shared.global [%0], [%1], 16;" :: "r"(dst), "l"(src));
    }
#pragma unroll
    for (int i = 0; i < 8; ++i) {
        int idx = tid + i * MIXT;
        int row = idx >> 5, seg = idx & 31;
        const float* src = Yp + (size_t)(k0 + row) * Ll + seg * 4;
        uint32_t dst = smem_stage + A_BYTES + (uint32_t)(row * BS_STR + seg * 4) * 4;
        asm volatile("cp.async.cg.shared.global [%0], [%1], 16;" :: "r"(dst), "l"(src));
    }
    asm volatile("cp.async.commit_group;" ::: "memory");
}

__global__ void __launch_bounds__(MIXT, 2) mix_tc_kernel(float* __restrict__ out) {
    extern __shared__ char smx[];
    uint32_t sb;
    asm("{ .reg .u64 t; cvta.to.shared.u64 t, %1; cvt.u32.u64 %0, t; }" : "=r"(sb) : "l"(smx));
    int tid  = threadIdx.x;
    int lane = tid & 31, wid = tid >> 5;
    int warpM = wid >> 1, warpN = wid & 1;      // 2 x 2 warps, 64x64 each
    int g = lane >> 2, tg = lane & 3;

    int b     = blockIdx.z;
    int pTile = blockIdx.y * 128;
    int lTile = blockIdx.x * 128;
    const float* Wp = g_Wr + (size_t)pTile * Hh;
    const float* Yp = g_ymid + (size_t)b * Hh * Ll + lTile;
    float* Ob = out + (size_t)b * Hh * Ll;

    float acc[4][8][4];
#pragma unroll
    for (int mt = 0; mt < 4; ++mt)
#pragma unroll
        for (int nt = 0; nt < 8; ++nt)
#pragma unroll
            for (int r = 0; r < 4; ++r) acc[mt][nt][r] = 0.f;

    // prologue: 2 chunks in flight
    load_stage(Wp, Yp, sb, 0, tid);
    load_stage(Wp, Yp, sb + STAGE_BYTES, 1, tid);

#pragma unroll 1
    for (int c = 0; c < NCHK; ++c) {
        // wait for chunk c (oldest); keep 1 group outstanding except at the tail
        if (c < NCHK - 2) {
            asm volatile("cp.async.wait_group 1;" ::: "memory");
        } else {
            asm volatile("cp.async.wait_group 0;" ::: "memory");
        }
        __syncthreads();
        if (c + 2 < NCHK)
            load_stage(Wp, Yp, sb + (uint32_t)((c + 2) % 3) * STAGE_BYTES, c + 2, tid);

        const float* As = (const float*)(smx + (c % 3) * STAGE_BYTES);
        const float* Bs = (const float*)(smx + (c % 3) * STAGE_BYTES + A_BYTES);
#pragma unroll
        for (int ks = 0; ks < 4; ++ks) {
            uint32_t af[4][4], bf[8][2];
            int kc = ks * 8 + tg;
#pragma unroll
            for (int mt = 0; mt < 4; ++mt) {
                int r0 = warpM * 64 + mt * 16 + g;
                af[mt][0] = __float_as_uint(As[r0 * AS_STR + kc]);
                af[mt][1] = __float_as_uint(As[(r0 + 8) * AS_STR + kc]);
                af[mt][2] = __float_as_uint(As[r0 * AS_STR + kc + 4]);
                af[mt][3] = __float_as_uint(As[(r0 + 8) * AS_STR + kc + 4]);
            }
#pragma unroll
            for (int nt = 0; nt < 8; ++nt) {
                int l = warpN * 64 + nt * 8 + g;
                bf[nt][0] = __float_as_uint(Bs[kc * BS_STR + l]);
                bf[nt][1] = __float_as_uint(Bs[(kc + 4) * BS_STR + l]);
            }
#pragma unroll
            for (int mt = 0; mt < 4; ++mt)
#pragma unroll
                for (int nt = 0; nt < 8; ++nt)
                    mma_tf32(acc[mt][nt], af[mt], bf[nt]);
        }
    }

    // epilogue: tanh + store
#pragma unroll
    for (int mt = 0; mt < 4; ++mt) {
        int p0 = pTile + warpM * 64 + mt * 16 + g;
#pragma unroll
        for (int nt = 0; nt < 8; ++nt) {
            int l = lTile + warpN * 64 + nt * 8 + 2 * tg;
            float2 v0 = make_float2(tanhf(acc[mt][nt][0]), tanhf(acc[mt][nt][1]));
            float2 v1 = make_float2(tanhf(acc[mt][nt][2]), tanhf(acc[mt][nt][3]));
            *(float2*)(Ob + (size_t)p0 * Ll + l)       = v0;
            *(float2*)(Ob + (size_t)(p0 + 8) * Ll + l) = v1;
        }
    }
}

// ---------------- launch ----------------
extern "C" void kernel_launch(void* const* d_in, const int* in_sizes, int n_in,
                              void* d_out, int out_size) {
    const float* u = (const float*)d_in[0];
    const float* K = (const float*)d_in[1];
    const float* D = (const float*)d_in[2];
    const float* W = (const float*)d_in[3];
    float* out = (float*)d_out;

    const int smem = NFFT * (int)sizeof(float2);  // 128 KB
    cudaFuncSetAttribute(kf_kernel,   cudaFuncAttributeMaxDynamicSharedMemorySize, smem);
    cudaFuncSetAttribute(conv_kernel, cudaFuncAttributeMaxDynamicSharedMemorySize, smem);
    cudaFuncSetAttribute(mix_tc_kernel, cudaFuncAttributeMaxDynamicSharedMemorySize, MIX_SMEM);

    tw_init<<<(NTW + 255) / 256, 256>>>();
    wround_kernel<<<(Hh * Hh) / 256, 256>>>(W);
    kf_kernel<<<NPAIR, TFFT, smem>>>(K);
    conv_kernel<<<Bb * NPAIR, TFFT, smem>>>(u, D);
    dim3 g(Ll / 128, Hh / 128, Bb);
    mix_tc_kernel<<<g, MIXT, MIX_SMEM>>>(out);
}

// round 16
// speedup vs baseline: 1.7528x; 1.0718x over previous
#include <cuda_runtime.h>
#include <cstdint>

#define Bb    8
#define Hh    512
#define Ll    8192
#define NFFT  16384
#define HALF  8192
#define QTOP  4096   /* NFFT/4 */
#define NPAIR 256    /* H/2 */
#define TFFT  512
#define NTW   5461   /* 1+4+16+...+4096 */

// ---------------- scratch (device globals; no allocation allowed) ----------------
__device__ float4 g_AB[(size_t)NPAIR * (HALF + 1)];   // per-pair spectra, pointwise iteration order
__device__ float  g_ymid[(size_t)Bb * Hh * Ll];       // conv+skip result (B,H,L), tf32-rounded
__device__ float  g_Wr[(size_t)Hh * Hh];              // W pre-rounded to tf32 (rna)
__device__ float2 g_tw1[NTW];                         // twiddle LUT per (stage,j)
__device__ float2 g_tw2[NTW];
__device__ float2 g_tw3[NTW];

// ---------------- helpers ----------------
__device__ __forceinline__ float2 cmulf(float2 a, float2 b) {
    return make_float2(a.x * b.x - a.y * b.y, a.x * b.y + a.y * b.x);
}
__device__ __forceinline__ int rev4_14(int k) {
    unsigned r = __brev((unsigned)k) >> 18;
    return (int)(((r & 0x2AAAu) >> 1) | ((r & 0x1555u) << 1));
}
__device__ __forceinline__ float tf32r(float v) {
    uint32_t r;
    asm("cvt.rna.tf32.f32 %0, %1;" : "=r"(r) : "f"(v));
    return __uint_as_float(r);
}
// full-nibble bank swizzle: XOR bits[4:8) into bits[0:4)  (involution)
__device__ __forceinline__ int sw(int n) {
    return n ^ ((n >> 4) & 15);
}
// radix-4 DFT core
__device__ __forceinline__ void bf4(float2& a0, float2& a1, float2& a2, float2& a3) {
    float t0x = a0.x + a2.x, t0y = a0.y + a2.y;
    float t1x = a0.x - a2.x, t1y = a0.y - a2.y;
    float t2x = a1.x + a3.x, t2y = a1.y + a3.y;
    float t3x = a1.x - a3.x, t3y = a1.y - a3.y;
    a0 = make_float2(t0x + t2x, t0y + t2y);
    a1 = make_float2(t1x + t3y, t1y - t3x);   // t1 - i*t3
    a2 = make_float2(t0x - t2x, t0y - t2y);
    a3 = make_float2(t1x - t3y, t1y + t3x);   // t1 + i*t3
}

// ---------------- twiddle LUT init ----------------
__global__ void tw_init() {
    int idx = blockIdx.x * 256 + threadIdx.x;
    if (idx >= NTW) return;
    int q = 1, off = 0;
    while (idx >= off + q) { off += q; q <<= 2; }
    int j = idx - off;
    int m = q << 2;
    float ang = -6.283185307179586f * ((float)j / (float)m);
    float s1, c1, s2, c2, s3, c3;
    sincosf(ang, &s1, &c1);
    sincosf(2.0f * ang, &s2, &c2);
    sincosf(3.0f * ang, &s3, &c3);
    g_tw1[idx] = make_float2(c1, s1);
    g_tw2[idx] = make_float2(c2, s2);
    g_tw3[idx] = make_float2(c3, s3);
}

// ---------------- fused load + first DIF stage (m=NFFT, top half zero) ----------------
__device__ void dif_first_fused(float2* s, const float* __restrict__ f1,
                                const float* __restrict__ f2, int tid) {
#pragma unroll 4
    for (int i = tid; i < QTOP; i += TFFT) {
        float2 a0 = make_float2(f1[i], f2[i]);
        float2 a1 = make_float2(f1[i + QTOP], f2[i + QTOP]);
        float2 b0 = make_float2(a0.x + a1.x, a0.y + a1.y);
        float2 b1 = make_float2(a0.x + a1.y, a0.y - a1.x);   // a0 - i*a1
        float2 b2 = make_float2(a0.x - a1.x, a0.y - a1.y);
        float2 b3 = make_float2(a0.x - a1.y, a0.y + a1.x);   // a0 + i*a1
        float2 w1 = __ldg(&g_tw1[1365 + i]);
        float2 w2 = __ldg(&g_tw2[1365 + i]);
        float2 w3 = __ldg(&g_tw3[1365 + i]);
        int ib = i ^ ((i >> 4) & 15);   // sw(i); offsets 4096k don't touch bits[4:8)
        s[ib]            = b0;
        s[ib + QTOP]     = cmulf(b1, w1);
        s[ib + 2 * QTOP] = cmulf(b2, w2);
        s[ib + 3 * QTOP] = cmulf(b3, w3);
    }
    __syncthreads();
}

// ---------------- merged radix-16 DIF pass: stages (m=4Q) then (m=Q), Q4 = Q/4 ----------------
// Q=1024: m=4096,1024 | Q=64: m=256,64 | Q=4: m=16,4 (contiguous 16-block per thread).
template<int Q>
__device__ __forceinline__ void dif_merged(float2* s, int tid) {
    constexpr int Q4   = Q / 4;
    constexpr int offA = (Q - 1) / 3;
    constexpr int offB = (Q4 - 1) / 3;
#pragma unroll 1
    for (int i = tid; i < NFFT / 16; i += TFFT) {
        int j  = i & (Q4 - 1);
        int g0 = (i / Q4) * (16 * Q4) + j;
        float2 x[16];
#pragma unroll
        for (int b = 0; b < 4; ++b) {
            float2 a0 = s[sw(g0 + b * Q4)];
            float2 a1 = s[sw(g0 + b * Q4 + Q)];
            float2 a2 = s[sw(g0 + b * Q4 + 2 * Q)];
            float2 a3 = s[sw(g0 + b * Q4 + 3 * Q)];
            bf4(a0, a1, a2, a3);
            int jA = j + b * Q4;
            float2 w1 = __ldg(&g_tw1[offA + jA]);
            float2 w2 = __ldg(&g_tw2[offA + jA]);
            float2 w3 = __ldg(&g_tw3[offA + jA]);
            x[b]      = a0;
            x[4 + b]  = cmulf(a1, w1);
            x[8 + b]  = cmulf(a2, w2);
            x[12 + b] = cmulf(a3, w3);
        }
        float2 v1 = __ldg(&g_tw1[offB + j]);
        float2 v2 = __ldg(&g_tw2[offB + j]);
        float2 v3 = __ldg(&g_tw3[offB + j]);
#pragma unroll
        for (int a = 0; a < 4; ++a) {
            bf4(x[4 * a], x[4 * a + 1], x[4 * a + 2], x[4 * a + 3]);
            int n0 = g0 + a * Q;
            s[sw(n0)]           = x[4 * a];
            s[sw(n0 + Q4)]      = cmulf(x[4 * a + 1], v1);
            s[sw(n0 + 2 * Q4)]  = cmulf(x[4 * a + 2], v2);
            s[sw(n0 + 3 * Q4)]  = cmulf(x[4 * a + 3], v3);
        }
    }
    __syncthreads();
}

// ---------------- merged radix-16 DIT pass: stages (m=Q) then (m=4Q) ----------------
template<int Q>
__device__ __forceinline__ void dit_merged(float2* s, int tid) {
    constexpr int Q4   = Q / 4;
    constexpr int offA = (Q - 1) / 3;
    constexpr int offB = (Q4 - 1) / 3;
#pragma unroll 1
    for (int i = tid; i < NFFT / 16; i += TFFT) {
        int j  = i & (Q4 - 1);
        int g0 = (i / Q4) * (16 * Q4) + j;
        float2 x[16];
        float2 v1 = __ldg(&g_tw1[offB + j]);
        float2 v2 = __ldg(&g_tw2[offB + j]);
        float2 v3 = __ldg(&g_tw3[offB + j]);
#pragma unroll
        for (int a = 0; a < 4; ++a) {
            int n0 = g0 + a * Q;
            float2 c0 = s[sw(n0)];
            float2 c1 = s[sw(n0 + Q4)];
            float2 c2 = s[sw(n0 + 2 * Q4)];
            float2 c3 = s[sw(n0 + 3 * Q4)];
            c1 = cmulf(c1, v1);
            c2 = cmulf(c2, v2);
            c3 = cmulf(c3, v3);
            bf4(c0, c1, c2, c3);
            x[4 * a]     = c0;
            x[4 * a + 1] = c1;
            x[4 * a + 2] = c2;
            x[4 * a + 3] = c3;
        }
#pragma unroll
        for (int b = 0; b < 4; ++b) {
            int jA = j + b * Q4;
            float2 w1 = __ldg(&g_tw1[offA + jA]);
            float2 w2 = __ldg(&g_tw2[offA + jA]);
            float2 w3 = __ldg(&g_tw3[offA + jA]);
            float2 c0 = x[b];
            float2 c1 = cmulf(x[4 + b],  w1);
            float2 c2 = cmulf(x[8 + b],  w2);
            float2 c3 = cmulf(x[12 + b], w3);
            bf4(c0, c1, c2, c3);
            int n0 = g0 + b * Q4;
            s[sw(n0)]         = c0;
            s[sw(n0 + Q)]     = c1;
            s[sw(n0 + 2 * Q)] = c2;
            s[sw(n0 + 3 * Q)] = c3;
        }
    }
    __syncthreads();
}

// ---------------- kernel 1: combined kernel spectra A,B per channel pair ----------------
__global__ void __launch_bounds__(TFFT, 1) kf_kernel(const float* __restrict__ K) {
    extern __shared__ float2 s[];
    int tid  = threadIdx.x;
    int pair = blockIdx.x;
    const float* k1 = K + (size_t)(2 * pair) * Ll;
    const float* k2 = K + (size_t)(2 * pair + 1) * Ll;
    dif_first_fused(s, k1, k2, tid);
    dif_merged<1024>(s, tid);
    dif_merged<64>(s, tid);
    dif_merged<4>(s, tid);

    const float inv = 1.0f / (4.0f * (float)NFFT);
    float4* AB = g_AB + (size_t)pair * (HALF + 1);
#pragma unroll 4
    for (int i = tid; i < HALF; i += TFFT) {
        int p  = ((i >> 1) << 2) | (i & 1);
        int k  = rev4_14(p);
        int kn = (NFFT - k) & (NFFT - 1);
        int p2 = rev4_14(kn);
        float2 Z  = s[sw(p)];
        float2 Zp = s[sw(p2)];
        float ax = (Z.x + Z.y + Zp.x + Zp.y) * inv;
        float ay = (Z.y - Z.x + Zp.x - Zp.y) * inv;
        float bx = (Z.x - Z.y + Zp.x - Zp.y) * inv;
        float by = (Z.x + Z.y - Zp.x - Zp.y) * inv;
        AB[i] = make_float4(ax, ay, bx, by);
    }
    if (tid == 0) {  // k = 8192 (slot 2), self-paired: Zp = Z
        float2 Z = s[sw(2)];
        float ax = 2.f * (Z.x + Z.y) * inv;
        float bx = 2.f * (Z.x - Z.y) * inv;
        AB[HALF] = make_float4(ax, 0.f, bx, 0.f);
    }
}

// ---------------- kernel 2: FFT conv + skip per (batch, channel pair) ----------------
__global__ void __launch_bounds__(TFFT, 1) conv_kernel(const float* __restrict__ u,
                                                       const float* __restrict__ D) {
    extern __shared__ float2 s[];
    int tid  = threadIdx.x;
    int pair = blockIdx.x & (NPAIR - 1);
    int b    = blockIdx.x >> 8;
    int h1   = 2 * pair, h2 = h1 + 1;
    const float* u1 = u + ((size_t)b * Hh + h1) * Ll;
    const float* u2 = u + ((size_t)b * Hh + h2) * Ll;
    dif_first_fused(s, u1, u2, tid);
    dif_merged<1024>(s, tid);
    dif_merged<64>(s, tid);
    dif_merged<4>(s, tid);

    // pointwise in slot order: p = 4*(i>>1)+(i&1) covers exactly k in [0,8192)
    const float4* AB = g_AB + (size_t)pair * (HALF + 1);
#pragma unroll 4
    for (int i = tid; i < HALF; i += TFFT) {
        int p  = ((i >> 1) << 2) | (i & 1);
        int k  = rev4_14(p);
        int kn = (NFFT - k) & (NFFT - 1);
        int p2 = rev4_14(kn);
        int sp = sw(p), sp2 = sw(p2);
        float2 Z  = s[sp];
        float2 Zp = s[sp2];
        float4 ab = AB[i];
        float vx = Z.x * ab.x - Z.y * ab.y + Zp.x * ab.z + Zp.y * ab.w;
        float vy = Z.x * ab.y + Z.y * ab.x - Zp.y * ab.z + Zp.x * ab.w;
        s[sp] = make_float2(vx, -vy);
        if (p != 0) {
            float wx =  Zp.x * ab.x + Zp.y * ab.y + Z.x * ab.z - Z.y * ab.w;
            float wy = -Zp.x * ab.y + Zp.y * ab.x - Z.x * ab.w - Z.y * ab.z;
            s[sp2] = make_float2(wx, -wy);
        }
    }
    if (tid == 0) {  // k = 8192 (slot 2), self-paired
        float2 Z = s[sw(2)];
        float4 ab = AB[HALF];
        float vx = Z.x * ab.x - Z.y * ab.y + Z.x * ab.z + Z.y * ab.w;
        float vy = Z.x * ab.y + Z.y * ab.x - Z.y * ab.z + Z.x * ab.w;
        s[sw(2)] = make_float2(vx, -vy);
    }
    __syncthreads();

    dit_merged<4>(s, tid);
    dit_merged<64>(s, tid);
    dit_merged<1024>(s, tid);

    // fused last DIT stage (m=NFFT): only outputs n<8192 kept; write y directly.
    float d1 = D[h1], d2 = D[h2];
    float* y1 = g_ymid + ((size_t)b * Hh + h1) * Ll;
    float* y2 = g_ymid + ((size_t)b * Hh + h2) * Ll;
#pragma unroll 4
    for (int i = tid; i < QTOP; i += TFFT) {
        int ib = i ^ ((i >> 4) & 15);   // sw(i); offsets 4096k share it
        float2 c0 = s[ib], c1 = s[ib + QTOP], c2 = s[ib + 2 * QTOP], c3 = s[ib + 3 * QTOP];
        float2 w1 = __ldg(&g_tw1[1365 + i]);
        float2 w2 = __ldg(&g_tw2[1365 + i]);
        float2 w3 = __ldg(&g_tw3[1365 + i]);
        c1 = cmulf(c1, w1);
        c2 = cmulf(c2, w2);
        c3 = cmulf(c3, w3);
        float t0x = c0.x + c2.x, t0y = c0.y + c2.y;
        float t1x = c0.x - c2.x, t1y = c0.y - c2.y;
        float t2x = c1.x + c3.x, t2y = c1.y + c3.y;
        float t3x = c1.x - c3.x, t3y = c1.y - c3.y;
        float o0x = t0x + t2x, o0y = t0y + t2y;
        float o1x = t1x + t3y, o1y = t1y - t3x;
        y1[i]        = tf32r( o0x + d1 * u1[i]);
        y2[i]        = tf32r(-o0y + d2 * u2[i]);
        y1[i + QTOP] = tf32r( o1x + d1 * u1[i + QTOP]);
        y2[i + QTOP] = tf32r(-o1y + d2 * u2[i + QTOP]);
    }
}

// ---------------- kernel 2.5: pre-round W to tf32 (round-to-nearest) ----------------
__global__ void wround_kernel(const float* __restrict__ W) {
    int i = blockIdx.x * 256 + threadIdx.x;
    g_Wr[i] = tf32r(W[i]);
}

// ================= kernel 3: tf32 mma.sync mix GEMM + tanh =================
// CTA tile 128p x 128l, 4 warps (warp tile 64x64), BK=32, 3-stage cp.async pipeline.
#define MIXT 128
#define NCHK (Hh / 32)                 /* 16 */
#define AS_STR 36
#define BS_STR 136
#define A_BYTES (128 * AS_STR * 4)
#define B_BYTES (32 * BS_STR * 4)
#define STAGE_BYTES (A_BYTES + B_BYTES)
#define MIX_SMEM (3 * STAGE_BYTES)     /* 107520 */

__device__ __forceinline__ void mma_tf32(float* c, const uint32_t* a, const uint32_t* b) {
    asm volatile(
        "mma.sync.aligned.m16n8k8.row.col.f32.tf32.tf32.f32 "
        "{%0,%1,%2,%3}, {%4,%5,%6,%7}, {%8,%9}, {%0,%1,%2,%3};"
        : "+f"(c[0]), "+f"(c[1]), "+f"(c[2]), "+f"(c[3])
        : "r"(a[0]), "r"(a[1]), "r"(a[2]), "r"(a[3]), "r"(b[0]), "r"(b[1]));
}
__device__ __forceinline__ void load_stage(const float* __restrict__ Wp,
                                           const float* __restrict__ Yp,
                                           uint32_t smem_stage, int c, int tid) {
    int k0 = c * 32;
#pragma unroll
    for (int i = 0; i < 8; ++i) {
        int idx = tid + i * MIXT;
        int row = idx >> 3, seg = idx & 7;
        const float* src = Wp + (size_t)row * Hh + k0 + seg * 4;
        uint32_t dst = smem_stage + (uint32_t)(row * AS_STR + seg * 4) * 4;
        asm volatile("cp.async.cg.shared.global [%0], [%1], 16;" :: "r"(dst), "l"(src));
    }
#pragma unroll
    for (int i = 0; i < 8; ++i) {
        int idx = tid + i * MIXT;
        int row = idx >> 5, seg = idx & 31;
        const float* src = Yp + (size_t)(k0 + row) * Ll + seg * 4;
        uint32_t dst = smem_stage + A_BYTES + (uint32_t)(row * BS_STR + seg * 4) * 4;
        asm volatile("cp.async.cg.shared.global [%0], [%1], 16;" :: "r"(dst), "l"(src));
    }
    asm volatile("cp.async.commit_group;" ::: "memory");
}

__global__ void __launch_bounds__(MIXT, 2) mix_tc_kernel(float* __restrict__ out) {
    extern __shared__ char smx[];
    uint32_t sb;
    asm("{ .reg .u64 t; cvta.to.shared.u64 t, %1; cvt.u32.u64 %0, t; }" : "=r"(sb) : "l"(smx));
    int tid  = threadIdx.x;
    int lane = tid & 31, wid = tid >> 5;
    int warpM = wid >> 1, warpN = wid & 1;      // 2 x 2 warps, 64x64 each
    int g = lane >> 2, tg = lane & 3;

    int b     = blockIdx.z;
    int pTile = blockIdx.y * 128;
    int lTile = blockIdx.x * 128;
    const float* Wp = g_Wr + (size_t)pTile * Hh;
    const float* Yp = g_ymid + (size_t)b * Hh * Ll + lTile;
    float* Ob = out + (size_t)b * Hh * Ll;

    float acc[4][8][4];
#pragma unroll
    for (int mt = 0; mt < 4; ++mt)
#pragma unroll
        for (int nt = 0; nt < 8; ++nt)
#pragma unroll
            for (int r = 0; r < 4; ++r) acc[mt][nt][r] = 0.f;

    // prologue: 2 chunks in flight
    load_stage(Wp, Yp, sb, 0, tid);
    load_stage(Wp, Yp, sb + STAGE_BYTES, 1, tid);

#pragma unroll 1
    for (int c = 0; c < NCHK; ++c) {
        if (c < NCHK - 2) {
            asm volatile("cp.async.wait_group 1;" ::: "memory");
        } else {
            asm volatile("cp.async.wait_group 0;" ::: "memory");
        }
        __syncthreads();
        if (c + 2 < NCHK)
            load_stage(Wp, Yp, sb + (uint32_t)((c + 2) % 3) * STAGE_BYTES, c + 2, tid);

        const float* As = (const float*)(smx + (c % 3) * STAGE_BYTES);
        const float* Bs = (const float*)(smx + (c % 3) * STAGE_BYTES + A_BYTES);
#pragma unroll
        for (int ks = 0; ks < 4; ++ks) {
            uint32_t af[4][4], bf[8][2];
            int kc = ks * 8 + tg;
#pragma unroll
            for (int mt = 0; mt < 4; ++mt) {
                int r0 = warpM * 64 + mt * 16 + g;
                af[mt][0] = __float_as_uint(As[r0 * AS_STR + kc]);
                af[mt][1] = __float_as_uint(As[(r0 + 8) * AS_STR + kc]);
                af[mt][2] = __float_as_uint(As[r0 * AS_STR + kc + 4]);
                af[mt][3] = __float_as_uint(As[(r0 + 8) * AS_STR + kc + 4]);
            }
#pragma unroll
            for (int nt = 0; nt < 8; ++nt) {
                int l = warpN * 64 + nt * 8 + g;
                bf[nt][0] = __float_as_uint(Bs[kc * BS_STR + l]);
                bf[nt][1] = __float_as_uint(Bs[(kc + 4) * BS_STR + l]);
            }
#pragma unroll
            for (int mt = 0; mt < 4; ++mt)
#pragma unroll
                for (int nt = 0; nt < 8; ++nt)
                    mma_tf32(acc[mt][nt], af[mt], bf[nt]);
        }
    }

    // epilogue: tanh + store
#pragma unroll
    for (int mt = 0; mt < 4; ++mt) {
        int p0 = pTile + warpM * 64 + mt * 16 + g;
#pragma unroll
        for (int nt = 0; nt < 8; ++nt) {
            int l = lTile + warpN * 64 + nt * 8 + 2 * tg;
            float2 v0 = make_float2(tanhf(acc[mt][nt][0]), tanhf(acc[mt][nt][1]));
            float2 v1 = make_float2(tanhf(acc[mt][nt][2]), tanhf(acc[mt][nt][3]));
            *(float2*)(Ob + (size_t)p0 * Ll + l)       = v0;
            *(float2*)(Ob + (size_t)(p0 + 8) * Ll + l) = v1;
        }
    }
}

// ---------------- launch ----------------
extern "C" void kernel_launch(void* const* d_in, const int* in_sizes, int n_in,
                              void* d_out, int out_size) {
    const float* u = (const float*)d_in[0];
    const float* K = (const float*)d_in[1];
    const float* D = (const float*)d_in[2];
    const float* W = (const float*)d_in[3];
    float* out = (float*)d_out;

    const int smem = NFFT * (int)sizeof(float2);  // 128 KB
    cudaFuncSetAttribute(kf_kernel,   cudaFuncAttributeMaxDynamicSharedMemorySize, smem);
    cudaFuncSetAttribute(conv_kernel, cudaFuncAttributeMaxDynamicSharedMemorySize, smem);
    cudaFuncSetAttribute(mix_tc_kernel, cudaFuncAttributeMaxDynamicSharedMemorySize, MIX_SMEM);

    tw_init<<<(NTW + 255) / 256, 256>>>();
    wround_kernel<<<(Hh * Hh) / 256, 256>>>(W);
    kf_kernel<<<NPAIR, TFFT, smem>>>(K);
    conv_kernel<<<Bb * NPAIR, TFFT, smem>>>(u, D);
    dim3 g(Ll / 128, Hh / 128, Bb);
    mix_tc_kernel<<<g, MIXT, MIX_SMEM>>>(out);
}